// round 8
// baseline (speedup 1.0000x reference)
#include <cuda_runtime.h>
#include <math.h>
#include <stdint.h>

#define N_TOK 32768
#define DIM   768
#define HID   3072
#define NEXP  8
#define CAP   10240
#define MTILES (CAP / 128)          // 80 (A/H blob granularity stays 128 rows)
#define KCH1  (DIM / 32)            // 24
#define KCH2  (HID / 32)            // 96

// ---------------------------------------------------------------------------
// Scratch (device globals)
// Fragment-blob layout: a 16KB blob = [sub][t(32)][j(4)] float units
//   A-blob (128m x 32k):  unit q = (m16blk*4 + ks)*32 + t
//   B-blob (32k x 128n):  unit q = (ks*8 + p)*32 + t
// ---------------------------------------------------------------------------
__device__ int   g_cnt[NEXP];
__device__ int   g_route_e[N_TOK * 2];
__device__ float g_route_w[N_TOK * 2];
__device__ int   g_tokidx[NEXP * CAP];
__device__ int   g_slot[N_TOK * 2];
__device__ float g_xg [(size_t)NEXP * MTILES * KCH1 * 4096];
__device__ float g_w1f[(size_t)NEXP * (HID/128) * KCH1 * 4096];
__device__ float g_w2f[(size_t)NEXP * (DIM/128) * KCH2 * 4096];
__device__ float g_H  [(size_t)NEXP * MTILES * KCH2 * 4096];
__device__ float g_Y  [(size_t)NEXP * CAP * DIM];

// ---------------------------------------------------------------------------
// Helpers
// ---------------------------------------------------------------------------
__device__ __forceinline__ float tf32r(float x) {
    uint32_t u;
    asm("cvt.rna.tf32.f32 %0, %1;" : "=r"(u) : "f"(x));
    return __uint_as_float(u);
}
__device__ __forceinline__ void cp16(void* dst, const float* src) {
    uint32_t d;
    asm("{ .reg .u64 t; cvta.to.shared.u64 t, %1; cvt.u32.u64 %0, t; }" : "=r"(d) : "l"(dst));
    asm volatile("cp.async.cg.shared.global [%0], [%1], 16;" :: "r"(d), "l"(src));
}
#define CP_COMMIT() asm volatile("cp.async.commit_group;" ::: "memory")
#define CP_WAIT1()  asm volatile("cp.async.wait_group 1;" ::: "memory")

#define MMA_TF32(c, a, b) \
    asm volatile("mma.sync.aligned.m16n8k8.row.col.f32.tf32.tf32.f32 " \
        "{%0,%1,%2,%3}, {%4,%5,%6,%7}, {%8,%9}, {%0,%1,%2,%3};" \
        : "+f"((c)[0]), "+f"((c)[1]), "+f"((c)[2]), "+f"((c)[3]) \
        : "r"((a)[0]), "r"((a)[1]), "r"((a)[2]), "r"((a)[3]), \
          "r"((b)[0]), "r"((b)[1]))

// ---------------------------------------------------------------------------
// Kernel 0: zero counters
// ---------------------------------------------------------------------------
__global__ void zero_counts_kernel() {
    if (threadIdx.x < NEXP) g_cnt[threadIdx.x] = 0;
}

// ---------------------------------------------------------------------------
// Kernel 1: router (one warp per token, exact fp32)
// ---------------------------------------------------------------------------
__global__ __launch_bounds__(256) void router_kernel(
    const float* __restrict__ x, const float* __restrict__ wg)
{
    int warp = (blockIdx.x * blockDim.x + threadIdx.x) >> 5;
    int lane = threadIdx.x & 31;
    if (warp >= N_TOK) return;
    const float* xr = x + (size_t)warp * DIM;

    float acc[NEXP];
#pragma unroll
    for (int e = 0; e < NEXP; e++) acc[e] = 0.f;
    for (int j = lane; j < DIM; j += 32) {
        float xv = xr[j];
        const float* wr = wg + j * NEXP;
#pragma unroll
        for (int e = 0; e < NEXP; e++) acc[e] += xv * wr[e];
    }
#pragma unroll
    for (int e = 0; e < NEXP; e++) {
#pragma unroll
        for (int o = 16; o > 0; o >>= 1)
            acc[e] += __shfl_xor_sync(0xffffffffu, acc[e], o);
    }
    if (lane == 0) {
        int e0 = 0; float v0 = acc[0];
#pragma unroll
        for (int e = 1; e < NEXP; e++) if (acc[e] > v0) { v0 = acc[e]; e0 = e; }
        int e1 = -1; float v1 = -3.4e38f;
#pragma unroll
        for (int e = 0; e < NEXP; e++) if (e != e0 && acc[e] > v1) { v1 = acc[e]; e1 = e; }
        float ex = expf(v1 - v0);
        float s  = 1.f + ex;
        g_route_e[2 * warp + 0] = e0;  g_route_w[2 * warp + 0] = 1.f / s;
        g_route_e[2 * warp + 1] = e1;  g_route_w[2 * warp + 1] = ex / s;
    }
}

// ---------------------------------------------------------------------------
// Kernel 2: slot assignment
// ---------------------------------------------------------------------------
__global__ void assign_kernel() {
    int t = blockIdx.x * blockDim.x + threadIdx.x;
    if (t >= N_TOK) return;
#pragma unroll
    for (int k = 0; k < 2; k++) {
        int e = g_route_e[2 * t + k];
        int pos = atomicAdd(&g_cnt[e], 1);
        if (pos < CAP) {
            g_tokidx[e * CAP + pos] = t;
            g_slot[2 * t + k] = e * CAP + pos;
        } else {
            g_slot[2 * t + k] = -1;
        }
    }
}

// ---------------------------------------------------------------------------
// Kernel 3: weight -> B-blob transform + tf32 round
// ---------------------------------------------------------------------------
__global__ __launch_bounds__(128) void wtransform_kernel(
    const float* __restrict__ w, float* __restrict__ out, int KD, int ND)
{
    const int nkc = KD / 32;
    const int e  = blockIdx.y;
    const int nt = blockIdx.x / nkc;
    const int kc = blockIdx.x % nkc;
    __shared__ float tile[32][132];

    const int tid = threadIdx.x;
    const float* src = w + ((size_t)e * KD + kc * 32) * ND + nt * 128;
#pragma unroll
    for (int u = tid; u < 1024; u += 128) {
        int r = u >> 5, c = (u & 31) * 4;
        float4 v = *(const float4*)(src + (size_t)r * ND + c);
        tile[r][c + 0] = tf32r(v.x);
        tile[r][c + 1] = tf32r(v.y);
        tile[r][c + 2] = tf32r(v.z);
        tile[r][c + 3] = tf32r(v.w);
    }
    __syncthreads();

    float4* dst = (float4*)(out + ((size_t)(e * (ND / 128) + nt) * nkc + kc) * 4096);
#pragma unroll
    for (int u = tid; u < 1024; u += 128) {
        int t = u & 31, p = (u >> 5) & 7, ks = u >> 8;
        int gid = t >> 2, tig = t & 3;
        float4 v;
        v.x = tile[ks * 8 + tig    ][p * 16 + gid];
        v.y = tile[ks * 8 + tig + 4][p * 16 + gid];
        v.z = tile[ks * 8 + tig    ][p * 16 + 8 + gid];
        v.w = tile[ks * 8 + tig + 4][p * 16 + 8 + gid];
        dst[u] = v;
    }
}

// ---------------------------------------------------------------------------
// Kernel 4: gather routed tokens into A-blobs (tf32-rounded)
// ---------------------------------------------------------------------------
__global__ __launch_bounds__(256) void gather_frag_kernel(const float* __restrict__ x) {
    const int e = blockIdx.y;
    const int Me = min(g_cnt[e], CAP);
    const int g16 = blockIdx.x;
    const int base = g16 * 16;
    if (base >= Me) return;

    __shared__ float rows[16][772];
    const int tid = threadIdx.x;

    for (int u = tid; u < 16 * 192; u += 256) {
        int r = u / 192, c = (u % 192) * 4;
        int pos = base + r;
        if (pos < Me) {
            int tok = g_tokidx[e * CAP + pos];
            float4 v = *(const float4*)(x + (size_t)tok * DIM + c);
            rows[r][c + 0] = tf32r(v.x);
            rows[r][c + 1] = tf32r(v.y);
            rows[r][c + 2] = tf32r(v.z);
            rows[r][c + 3] = tf32r(v.w);
        } else {
            rows[r][c + 0] = 0.f; rows[r][c + 1] = 0.f;
            rows[r][c + 2] = 0.f; rows[r][c + 3] = 0.f;
        }
    }
    __syncthreads();

    const int mtile = g16 >> 3, m16blk = g16 & 7;
    float4* outb = (float4*)g_xg;
    for (int u = tid; u < 16 * 192; u += 256) {
        int kc = u >> 7, w = u & 127, t = w & 31;
        int ks = (w >> 5) & 3;
        int gid = t >> 2, tig = t & 3;
        int col = kc * 32 + ks * 8 + tig;
        float4 v;
        v.x = rows[gid    ][col];
        v.y = rows[gid + 8][col];
        v.z = rows[gid    ][col + 4];
        v.w = rows[gid + 8][col + 4];
        outb[((size_t)((e * MTILES + mtile) * KCH1 + kc)) * 1024 + m16blk * 128 + w] = v;
    }
}

// ---------------------------------------------------------------------------
// Fragment-major tf32 GEMM. CTA 256x128, 8 warps (4x2), warp tile 64x64.
//   acc[4][8][4] = 128 regs/thread. 3-stage cp.async pipeline, 48KB/stage.
//   Mainloop per warp-ks: 8 LDS.128 + 32 MMA.
// ---------------------------------------------------------------------------
template<int NKCH, int NDIM, bool EPI_FRAG>
__global__ __launch_bounds__(256, 1) void gemm_frag_kernel(
    const float* __restrict__ Ablobs,
    const float* __restrict__ Bblobs,
    const float* __restrict__ bias,
    float* __restrict__ Cout)
{
    const int e  = blockIdx.z;
    const int Me = min(g_cnt[e], CAP);
    const int m0 = blockIdx.y * 256;
    if (m0 >= Me) return;
    const int bx = blockIdx.x;
    const int mt0 = blockIdx.y * 2;       // first 128-row blob index

    extern __shared__ float smem[];       // 3 stages x 12288 floats (48KB)
    const int tid = threadIdx.x;
    const int wid = tid >> 5, lid = tid & 31;
    const int gid = lid >> 2, tig = lid & 3;
    const int wMblk = (wid >> 1) * 4;     // m16 block base (0,4,8,12)
    const int pbase = (wid & 1) * 4;      // B pair base (0 or 4)

    const float* Ab0 = Ablobs + ((size_t)(e * MTILES + mt0    ) * NKCH) * 4096;
    const float* Ab1 = Ablobs + ((size_t)(e * MTILES + mt0 + 1) * NKCH) * 4096;
    const float* Bb  = Bblobs + ((size_t)(e * (NDIM / 128) + bx) * NKCH) * 4096;

    float acc[4][8][4];
#pragma unroll
    for (int mf = 0; mf < 4; mf++)
#pragma unroll
        for (int nf = 0; nf < 8; nf++)
#pragma unroll
            for (int q = 0; q < 4; q++) acc[mf][nf][q] = 0.f;

    auto issue = [&](int i) {
        float* dst = smem + (i % 3) * 12288;
        const float* a0 = Ab0 + (size_t)i * 4096;
        const float* a1 = Ab1 + (size_t)i * 4096;
        const float* b  = Bb  + (size_t)i * 4096;
#pragma unroll
        for (int j = 0; j < 4; j++)
            cp16(dst + (j * 256 + tid) * 4, a0 + (j * 256 + tid) * 4);
#pragma unroll
        for (int j = 0; j < 4; j++)
            cp16(dst + 4096 + (j * 256 + tid) * 4, a1 + (j * 256 + tid) * 4);
#pragma unroll
        for (int j = 0; j < 4; j++)
            cp16(dst + 8192 + (j * 256 + tid) * 4, b + (j * 256 + tid) * 4);
        CP_COMMIT();
    };

    issue(0);
    issue(1);

    for (int i = 0; i < NKCH; i++) {
        CP_WAIT1();
        __syncthreads();
        if (i + 2 < NKCH) issue(i + 2); else CP_COMMIT();

        const float4* pA = (const float4*)(smem + (i % 3) * 12288);  // 2048 f4 (2 blobs)
        const float4* pB = pA + 2048;
#pragma unroll
        for (int ks = 0; ks < 4; ks++) {
            uint32_t a[4][4], b[8][2];
#pragma unroll
            for (int mf = 0; mf < 4; mf++) {
                float4 v = pA[((wMblk + mf) * 4 + ks) * 32 + lid];
                a[mf][0] = __float_as_uint(v.x);
                a[mf][1] = __float_as_uint(v.y);
                a[mf][2] = __float_as_uint(v.z);
                a[mf][3] = __float_as_uint(v.w);
            }
#pragma unroll
            for (int q = 0; q < 4; q++) {
                float4 v = pB[(ks * 8 + pbase + q) * 32 + lid];
                b[2 * q + 0][0] = __float_as_uint(v.x);
                b[2 * q + 0][1] = __float_as_uint(v.y);
                b[2 * q + 1][0] = __float_as_uint(v.z);
                b[2 * q + 1][1] = __float_as_uint(v.w);
            }
#pragma unroll
            for (int mf = 0; mf < 4; mf++)
#pragma unroll
                for (int nf = 0; nf < 8; nf++)
                    MMA_TF32(acc[mf][nf], a[mf], b[nf]);
        }
    }

    const int warpM = (wid >> 1) * 64;    // 0,64,128,192
    const int warpN = (wid & 1) * 64;
    const int n0 = bx * 128;
    const float* bp = bias + (size_t)e * NDIM + n0 + warpN;

    if (EPI_FRAG) {
        // emit H blobs for mtiles mt0 (+h), kcs bx*4 .. bx*4+3; two 64KB halves
#pragma unroll
        for (int h = 0; h < 2; h++) {
            __syncthreads();
            if ((wid >> 2) == h) {
#pragma unroll
                for (int mf = 0; mf < 4; mf++)
#pragma unroll
                    for (int half = 0; half < 2; half++) {
                        int ml = warpM - h * 128 + mf * 16 + gid + half * 8; // 0..127
                        int mm = ml & 15, m16blk = ml >> 4;
#pragma unroll
                        for (int nf = 0; nf < 8; nf++)
#pragma unroll
                            for (int c = 0; c < 2; c++) {
                                int n_local = warpN + nf * 8 + tig * 2 + c;
                                float v = acc[mf][nf][half * 2 + c] + bp[nf * 8 + tig * 2 + c];
                                v = tf32r(0.5f * v * (1.f + erff(v * 0.70710678118654752f)));
                                int kc = n_local >> 5, ks = (n_local >> 3) & 3;
                                int t = (mm & 7) * 4 + (n_local & 3);
                                int j = ((n_local >> 2) & 1) * 2 + (mm >> 3);
                                int tw = t ^ (((t >> 3) & 3) << 1);
                                smem[(kc * 1024 + (m16blk * 4 + ks) * 32 + tw) * 4 + j] = v;
                            }
                    }
            }
            __syncthreads();
            float4* dst = (float4*)(Cout +
                ((size_t)((e * MTILES + mt0 + h) * KCH2 + bx * 4)) * 4096);
            const float4* st = (const float4*)smem;
#pragma unroll
            for (int u = tid; u < 4096; u += 256) {
                int t = u & 31;
                int tw = t ^ (((t >> 3) & 3) << 1);
                dst[u] = st[(u & ~31) | tw];
            }
        }
    } else {
#pragma unroll
        for (int mf = 0; mf < 4; mf++)
#pragma unroll
            for (int half = 0; half < 2; half++) {
                int m = m0 + warpM + mf * 16 + gid + half * 8;
                if (m >= Me) continue;
                float* Crow = Cout + (size_t)(e * CAP + m) * NDIM + n0 + warpN;
#pragma unroll
                for (int nf = 0; nf < 8; nf++) {
                    float2 o;
                    o.x = acc[mf][nf][half * 2 + 0] + bp[nf * 8 + tig * 2 + 0];
                    o.y = acc[mf][nf][half * 2 + 1] + bp[nf * 8 + tig * 2 + 1];
                    *(float2*)(Crow + nf * 8 + tig * 2) = o;
                }
            }
    }
}

// ---------------------------------------------------------------------------
// combine + LayerNorm
// ---------------------------------------------------------------------------
__global__ __launch_bounds__(256) void combine_ln_kernel(
    const float* __restrict__ lnw,
    const float* __restrict__ lnb,
    float* __restrict__ out)
{
    const int t   = blockIdx.x;
    const int tid = threadIdx.x;
    const int s0  = g_slot[2 * t + 0];
    const int s1  = g_slot[2 * t + 1];
    const float w0 = g_route_w[2 * t + 0];
    const float w1 = g_route_w[2 * t + 1];

    float v[3];
    float sum = 0.f;
#pragma unroll
    for (int r = 0; r < 3; r++) {
        int i = r * 256 + tid;
        float a = (s0 >= 0) ? g_Y[(size_t)s0 * DIM + i] : 0.f;
        float b = (s1 >= 0) ? g_Y[(size_t)s1 * DIM + i] : 0.f;
        v[r] = w0 * a + w1 * b;
        sum += v[r];
    }

    __shared__ float red[256];
    red[tid] = sum;
    __syncthreads();
#pragma unroll
    for (int o = 128; o > 0; o >>= 1) {
        if (tid < o) red[tid] += red[tid + o];
        __syncthreads();
    }
    float mu = red[0] * (1.f / (float)DIM);
    __syncthreads();

    float sq = 0.f;
#pragma unroll
    for (int r = 0; r < 3; r++) { float d = v[r] - mu; sq += d * d; }
    red[tid] = sq;
    __syncthreads();
#pragma unroll
    for (int o = 128; o > 0; o >>= 1) {
        if (tid < o) red[tid] += red[tid + o];
        __syncthreads();
    }
    float rstd = rsqrtf(red[0] * (1.f / (float)DIM) + 1e-5f);

#pragma unroll
    for (int r = 0; r < 3; r++) {
        int i = r * 256 + tid;
        out[(size_t)t * DIM + i] = (v[r] - mu) * rstd * lnw[i] + lnb[i];
    }
}

// ---------------------------------------------------------------------------
// Launch
// ---------------------------------------------------------------------------
extern "C" void kernel_launch(void* const* d_in, const int* in_sizes, int n_in,
                              void* d_out, int out_size)
{
    const float* x   = (const float*)d_in[0];
    const float* wg  = (const float*)d_in[1];
    const float* w1  = (const float*)d_in[2];
    const float* b1  = (const float*)d_in[3];
    const float* w2  = (const float*)d_in[4];
    const float* b2  = (const float*)d_in[5];
    const float* lnw = (const float*)d_in[6];
    const float* lnb = (const float*)d_in[7];
    float* out = (float*)d_out;

    const int SMEM_BYTES = 3 * 12288 * 4;   // 147456
    cudaFuncSetAttribute(gemm_frag_kernel<KCH1, HID, true>,
                         cudaFuncAttributeMaxDynamicSharedMemorySize, SMEM_BYTES);
    cudaFuncSetAttribute(gemm_frag_kernel<KCH2, DIM, false>,
                         cudaFuncAttributeMaxDynamicSharedMemorySize, SMEM_BYTES);

    float* w1f; cudaGetSymbolAddress((void**)&w1f, g_w1f);
    float* w2f; cudaGetSymbolAddress((void**)&w2f, g_w2f);
    float* xg;  cudaGetSymbolAddress((void**)&xg,  g_xg);
    float* Hbuf; cudaGetSymbolAddress((void**)&Hbuf, g_H);
    float* Ybuf; cudaGetSymbolAddress((void**)&Ybuf, g_Y);

    zero_counts_kernel<<<1, 32>>>();
    router_kernel<<<N_TOK / 8, 256>>>(x, wg);
    assign_kernel<<<N_TOK / 256, 256>>>();

    wtransform_kernel<<<dim3((HID / 128) * KCH1, NEXP), 128>>>(w1, w1f, DIM, HID);
    wtransform_kernel<<<dim3((DIM / 128) * KCH2, NEXP), 128>>>(w2, w2f, HID, DIM);

    gather_frag_kernel<<<dim3(CAP / 16, NEXP), 256>>>(x);

    gemm_frag_kernel<KCH1, HID, true><<<dim3(HID / 128, CAP / 256, NEXP), 256, SMEM_BYTES>>>(
        xg, w1f, b1, Hbuf);
    gemm_frag_kernel<KCH2, DIM, false><<<dim3(DIM / 128, CAP / 256, NEXP), 256, SMEM_BYTES>>>(
        Hbuf, w2f, b2, Ybuf);

    combine_ln_kernel<<<N_TOK, 256>>>(lnw, lnb, out);
}

// round 9
// speedup vs baseline: 2.2437x; 2.2437x over previous
#include <cuda_runtime.h>
#include <cuda_fp16.h>
#include <math.h>
#include <stdint.h>

#define N_TOK 32768
#define DIM   768
#define HID   3072
#define NEXP  8
#define CAP   10240
#define MTILES (CAP / 128)          // 80
#define KCH1  (DIM / 64)            // 12  (BK=64 chunks, GEMM1)
#define KCH2  (HID / 64)            // 48  (BK=64 chunks, GEMM2)

// ---------------------------------------------------------------------------
// Scratch. Fragment-major fp16 blobs, 16KB each (1024 float4 units):
//  A-blob (128m x 64k):  unit q=(m16blk*4+ks)*32+t ; word j: row=m16*16+gid+8*(j&1),
//                        k=ks*16+tig*2+{0,1}+8*(j>>1)      (m16n8k16 A frag regs)
//  B-blob (64k x 128n):  unit q=(ks*8+pp)*32+t ; word j: n=pp*16+8*(j>>1)+gid,
//                        k=ks*16+tig*2+{0,1}+8*(j&1)       (B frag regs b0/b1, pair pp)
// ---------------------------------------------------------------------------
__device__ int    g_cnt[NEXP];
__device__ int    g_route_e[N_TOK * 2];
__device__ float  g_route_w[N_TOK * 2];
__device__ int    g_tokidx[NEXP * CAP];
__device__ int    g_slot[N_TOK * 2];
__device__ __half g_xg [(size_t)NEXP * CAP * DIM];
__device__ __half g_w1f[(size_t)NEXP * DIM * HID];
__device__ __half g_w2f[(size_t)NEXP * HID * DIM];
__device__ __half g_H  [(size_t)NEXP * CAP * HID];
__device__ float  g_Y  [(size_t)NEXP * CAP * DIM];

// ---------------------------------------------------------------------------
// Helpers
// ---------------------------------------------------------------------------
__device__ __forceinline__ void cp16(void* dst, const void* src) {
    uint32_t d;
    asm("{ .reg .u64 t; cvta.to.shared.u64 t, %1; cvt.u32.u64 %0, t; }" : "=r"(d) : "l"(dst));
    asm volatile("cp.async.cg.shared.global [%0], [%1], 16;" :: "r"(d), "l"(src));
}
#define CP_COMMIT() asm volatile("cp.async.commit_group;" ::: "memory")
#define CP_WAIT1()  asm volatile("cp.async.wait_group 1;" ::: "memory")

#define MMA_F16(c, a, b) \
    asm volatile("mma.sync.aligned.m16n8k16.row.col.f32.f16.f16.f32 " \
        "{%0,%1,%2,%3}, {%4,%5,%6,%7}, {%8,%9}, {%0,%1,%2,%3};" \
        : "+f"((c)[0]), "+f"((c)[1]), "+f"((c)[2]), "+f"((c)[3]) \
        : "r"((a)[0]), "r"((a)[1]), "r"((a)[2]), "r"((a)[3]), \
          "r"((b)[0]), "r"((b)[1]))

// ---------------------------------------------------------------------------
// Kernel 0: zero counters
// ---------------------------------------------------------------------------
__global__ void zero_counts_kernel() {
    if (threadIdx.x < NEXP) g_cnt[threadIdx.x] = 0;
}

// ---------------------------------------------------------------------------
// Kernel 1: router (one warp per token, exact fp32)
// ---------------------------------------------------------------------------
__global__ __launch_bounds__(256) void router_kernel(
    const float* __restrict__ x, const float* __restrict__ wg)
{
    int warp = (blockIdx.x * blockDim.x + threadIdx.x) >> 5;
    int lane = threadIdx.x & 31;
    if (warp >= N_TOK) return;
    const float* xr = x + (size_t)warp * DIM;

    float acc[NEXP];
#pragma unroll
    for (int e = 0; e < NEXP; e++) acc[e] = 0.f;
    for (int j = lane; j < DIM; j += 32) {
        float xv = xr[j];
        const float* wr = wg + j * NEXP;
#pragma unroll
        for (int e = 0; e < NEXP; e++) acc[e] += xv * wr[e];
    }
#pragma unroll
    for (int e = 0; e < NEXP; e++) {
#pragma unroll
        for (int o = 16; o > 0; o >>= 1)
            acc[e] += __shfl_xor_sync(0xffffffffu, acc[e], o);
    }
    if (lane == 0) {
        int e0 = 0; float v0 = acc[0];
#pragma unroll
        for (int e = 1; e < NEXP; e++) if (acc[e] > v0) { v0 = acc[e]; e0 = e; }
        int e1 = -1; float v1 = -3.4e38f;
#pragma unroll
        for (int e = 0; e < NEXP; e++) if (e != e0 && acc[e] > v1) { v1 = acc[e]; e1 = e; }
        float ex = expf(v1 - v0);
        float s  = 1.f + ex;
        g_route_e[2 * warp + 0] = e0;  g_route_w[2 * warp + 0] = 1.f / s;
        g_route_e[2 * warp + 1] = e1;  g_route_w[2 * warp + 1] = ex / s;
    }
}

// ---------------------------------------------------------------------------
// Kernel 2: slot assignment
// ---------------------------------------------------------------------------
__global__ void assign_kernel() {
    int t = blockIdx.x * blockDim.x + threadIdx.x;
    if (t >= N_TOK) return;
#pragma unroll
    for (int k = 0; k < 2; k++) {
        int e = g_route_e[2 * t + k];
        int pos = atomicAdd(&g_cnt[e], 1);
        if (pos < CAP) {
            g_tokidx[e * CAP + pos] = t;
            g_slot[2 * t + k] = e * CAP + pos;
        } else {
            g_slot[2 * t + k] = -1;
        }
    }
}

// ---------------------------------------------------------------------------
// Kernel 3: weight -> fp16 B-blob transform.
//   One block per (e, ntile, kchunk): 64k x 128n tile.
// ---------------------------------------------------------------------------
__global__ __launch_bounds__(128) void wtransform_kernel(
    const float* __restrict__ w, __half* __restrict__ out, int KD, int ND)
{
    const int nkc = KD / 64;
    const int e  = blockIdx.y;
    const int nt = blockIdx.x / nkc;
    const int kc = blockIdx.x % nkc;
    __shared__ float tile[64][132];

    const int tid = threadIdx.x;
    const float* src = w + ((size_t)e * KD + kc * 64) * ND + nt * 128;
#pragma unroll
    for (int u = tid; u < 2048; u += 128) {       // float4 units
        int r = u >> 5, c = (u & 31) * 4;
        float4 v = *(const float4*)(src + (size_t)r * ND + c);
        tile[r][c + 0] = v.x; tile[r][c + 1] = v.y;
        tile[r][c + 2] = v.z; tile[r][c + 3] = v.w;
    }
    __syncthreads();

    float4* dst = (float4*)(out + (((size_t)(e * (ND / 128) + nt) * nkc + kc) << 13));
#pragma unroll
    for (int u = tid; u < 1024; u += 128) {
        int t = u & 31, pp = (u >> 5) & 7, ks = u >> 8;
        int gid = t >> 2, tig = t & 3;
        __half2 h[4];
#pragma unroll
        for (int j = 0; j < 4; j++) {
            int n = pp * 16 + 8 * (j >> 1) + gid;
            int k = ks * 16 + tig * 2 + 8 * (j & 1);
            h[j] = __floats2half2_rn(tile[k][n], tile[k + 1][n]);
        }
        float4 v;
        v.x = __uint_as_float(*(uint32_t*)&h[0]);
        v.y = __uint_as_float(*(uint32_t*)&h[1]);
        v.z = __uint_as_float(*(uint32_t*)&h[2]);
        v.w = __uint_as_float(*(uint32_t*)&h[3]);
        dst[u] = v;
    }
}

// ---------------------------------------------------------------------------
// Kernel 4: gather routed tokens into fp16 A-blobs.
//   One block per m16 group of 16 tokens.
// ---------------------------------------------------------------------------
__global__ __launch_bounds__(256) void gather_frag_kernel(const float* __restrict__ x) {
    const int e = blockIdx.y;
    const int Me = min(g_cnt[e], CAP);
    const int g16 = blockIdx.x;
    const int base = g16 * 16;
    if (base >= Me) return;

    __shared__ float rows[16][772];
    const int tid = threadIdx.x;

    for (int u = tid; u < 16 * 192; u += 256) {
        int r = u / 192, c = (u % 192) * 4;
        int pos = base + r;
        if (pos < Me) {
            int tok = g_tokidx[e * CAP + pos];
            float4 v = *(const float4*)(x + (size_t)tok * DIM + c);
            rows[r][c + 0] = v.x; rows[r][c + 1] = v.y;
            rows[r][c + 2] = v.z; rows[r][c + 3] = v.w;
        } else {
            rows[r][c + 0] = 0.f; rows[r][c + 1] = 0.f;
            rows[r][c + 2] = 0.f; rows[r][c + 3] = 0.f;
        }
    }
    __syncthreads();

    const int mtile = g16 >> 3, m16blk = g16 & 7;
    float4* outb = (float4*)g_xg;
    // 12 kchunks x 4 ks x 32 t = 1536 float4 units for this m16 block
    for (int u = tid; u < 1536; u += 256) {
        int kc = u >> 7, r = u & 127;
        int ks = r >> 5, t = r & 31;
        int gid = t >> 2, tig = t & 3;
        __half2 h[4];
#pragma unroll
        for (int j = 0; j < 4; j++) {
            int row = gid + 8 * (j & 1);
            int col = kc * 64 + ks * 16 + tig * 2 + 8 * (j >> 1);
            h[j] = __floats2half2_rn(rows[row][col], rows[row][col + 1]);
        }
        float4 v;
        v.x = __uint_as_float(*(uint32_t*)&h[0]);
        v.y = __uint_as_float(*(uint32_t*)&h[1]);
        v.z = __uint_as_float(*(uint32_t*)&h[2]);
        v.w = __uint_as_float(*(uint32_t*)&h[3]);
        outb[(((size_t)((e * MTILES + mtile) * KCH1 + kc)) << 10) + m16blk * 128 + ks * 32 + t] = v;
    }
}

// ---------------------------------------------------------------------------
// fp16 fragment-major GEMM. CTA 128x128, 8 warps (4x2), warp tile 32x64.
//   BK=64 chunk = A-blob 16KB + B-blob 16KB. 3-stage cp.async (96KB, 2 CTA/SM).
//   Mainloop per warp-ks: 6 LDS.128 + 16 MMA (m16n8k16).
// ---------------------------------------------------------------------------
template<int NKCH, int NDIM, bool EPI_FRAG>
__global__ __launch_bounds__(256, 2) void gemm_f16_kernel(
    const __half* __restrict__ Ablobs,
    const __half* __restrict__ Bblobs,
    const float* __restrict__ bias,
    void* __restrict__ Cout)
{
    const int e  = blockIdx.z;
    const int Me = min(g_cnt[e], CAP);
    const int m0 = blockIdx.y * 128;
    if (m0 >= Me) return;
    const int bx = blockIdx.x;

    extern __shared__ float smem[];           // 3 stages x 8192 floats (32KB)
    const int tid = threadIdx.x;
    const int wid = tid >> 5, lid = tid & 31;
    const int gid = lid >> 2, tig = lid & 3;
    const int wMblk = (wid >> 1) * 2;         // m16 block base (0,2,4,6)
    const int pbase = (wid & 1) * 4;          // B pair base (0 or 4)

    const float4* Ab = (const float4*)(Ablobs + (((size_t)(e * MTILES + blockIdx.y) * NKCH) << 13));
    const float4* Bb = (const float4*)(Bblobs + (((size_t)(e * (NDIM / 128) + bx) * NKCH) << 13));

    float acc[2][8][4];
#pragma unroll
    for (int mf = 0; mf < 2; mf++)
#pragma unroll
        for (int nf = 0; nf < 8; nf++)
#pragma unroll
            for (int q = 0; q < 4; q++) acc[mf][nf][q] = 0.f;

    auto issue = [&](int i) {
        float4* dst = (float4*)(smem + (i % 3) * 8192);
        const float4* a = Ab + ((size_t)i << 10);
        const float4* b = Bb + ((size_t)i << 10);
#pragma unroll
        for (int j = 0; j < 4; j++)
            cp16(dst + j * 256 + tid, a + j * 256 + tid);
#pragma unroll
        for (int j = 0; j < 4; j++)
            cp16(dst + 1024 + j * 256 + tid, b + j * 256 + tid);
        CP_COMMIT();
    };

    issue(0);
    issue(1);

    for (int i = 0; i < NKCH; i++) {
        CP_WAIT1();
        __syncthreads();
        if (i + 2 < NKCH) issue(i + 2); else CP_COMMIT();

        const float4* pA = (const float4*)(smem + (i % 3) * 8192);
        const float4* pB = pA + 1024;
#pragma unroll
        for (int ks = 0; ks < 4; ks++) {
            uint32_t a[2][4], b[8][2];
#pragma unroll
            for (int mf = 0; mf < 2; mf++) {
                float4 v = pA[((wMblk + mf) * 4 + ks) * 32 + lid];
                a[mf][0] = __float_as_uint(v.x);
                a[mf][1] = __float_as_uint(v.y);
                a[mf][2] = __float_as_uint(v.z);
                a[mf][3] = __float_as_uint(v.w);
            }
#pragma unroll
            for (int q = 0; q < 4; q++) {
                float4 v = pB[(ks * 8 + pbase + q) * 32 + lid];
                b[2 * q + 0][0] = __float_as_uint(v.x);
                b[2 * q + 0][1] = __float_as_uint(v.y);
                b[2 * q + 1][0] = __float_as_uint(v.z);
                b[2 * q + 1][1] = __float_as_uint(v.w);
            }
#pragma unroll
            for (int mf = 0; mf < 2; mf++)
#pragma unroll
                for (int nf = 0; nf < 8; nf++)
                    MMA_F16(acc[mf][nf], a[mf], b[nf]);
        }
    }

    const int warpM = (wid >> 1) * 32;
    const int warpN = (wid & 1) * 64;
    const int n0 = bx * 128;
    const float* bp = bias + (size_t)e * NDIM + n0 + warpN;

    if (EPI_FRAG) {
        // gelu -> fp16 H blobs (GEMM2 A layout), staged via smem (2 blobs = 32KB)
        __syncthreads();
#pragma unroll
        for (int mf = 0; mf < 2; mf++)
#pragma unroll
            for (int half = 0; half < 2; half++) {
                int m_local = warpM + mf * 16 + gid + half * 8;
                int m16blk = m_local >> 4, mm = m_local & 15;
                int gid_a = mm & 7, ja_lo = mm >> 3;
#pragma unroll
                for (int nf = 0; nf < 8; nf++) {
                    int n_local = warpN + nf * 8 + tig * 2;
                    float v0 = acc[mf][nf][half * 2 + 0] + bp[nf * 8 + tig * 2 + 0];
                    float v1 = acc[mf][nf][half * 2 + 1] + bp[nf * 8 + tig * 2 + 1];
                    v0 = 0.5f * v0 * (1.f + erff(v0 * 0.70710678118654752f));
                    v1 = 0.5f * v1 * (1.f + erff(v1 * 0.70710678118654752f));
                    __half2 hv = __floats2half2_rn(v0, v1);
                    int kc_l = n_local >> 6;
                    int kin  = n_local & 63;
                    int ks = kin >> 4, kk = kin & 15;
                    int ja_hi = kk >> 3, tig_a = (kk & 7) >> 1;
                    int t_a = gid_a * 4 + tig_a;
                    int tw = t_a ^ (((t_a >> 3) & 3) << 1);
                    int q = kc_l * 1024 + (m16blk * 4 + ks) * 32 + tw;
                    ((__half2*)smem)[q * 4 + (ja_lo + 2 * ja_hi)] = hv;
                }
            }
        __syncthreads();
        float4* dst = (float4*)((__half*)Cout +
            (((size_t)((e * MTILES + blockIdx.y) * KCH2 + bx * 2)) << 13));
        const float4* st = (const float4*)smem;
#pragma unroll
        for (int u = tid; u < 2048; u += 256) {
            int t = u & 31;
            int tw = t ^ (((t >> 3) & 3) << 1);
            dst[u] = st[(u & ~31) | tw];
        }
    } else {
        float* Cf = (float*)Cout;
#pragma unroll
        for (int mf = 0; mf < 2; mf++)
#pragma unroll
            for (int half = 0; half < 2; half++) {
                int m = m0 + warpM + mf * 16 + gid + half * 8;
                if (m >= Me) continue;
                float* Crow = Cf + (size_t)(e * CAP + m) * NDIM + n0 + warpN;
#pragma unroll
                for (int nf = 0; nf < 8; nf++) {
                    float2 o;
                    o.x = acc[mf][nf][half * 2 + 0] + bp[nf * 8 + tig * 2 + 0];
                    o.y = acc[mf][nf][half * 2 + 1] + bp[nf * 8 + tig * 2 + 1];
                    *(float2*)(Crow + nf * 8 + tig * 2) = o;
                }
            }
    }
}

// ---------------------------------------------------------------------------
// combine + LayerNorm
// ---------------------------------------------------------------------------
__global__ __launch_bounds__(256) void combine_ln_kernel(
    const float* __restrict__ lnw,
    const float* __restrict__ lnb,
    float* __restrict__ out)
{
    const int t   = blockIdx.x;
    const int tid = threadIdx.x;
    const int s0  = g_slot[2 * t + 0];
    const int s1  = g_slot[2 * t + 1];
    const float w0 = g_route_w[2 * t + 0];
    const float w1 = g_route_w[2 * t + 1];

    float v[3];
    float sum = 0.f;
#pragma unroll
    for (int r = 0; r < 3; r++) {
        int i = r * 256 + tid;
        float a = (s0 >= 0) ? g_Y[(size_t)s0 * DIM + i] : 0.f;
        float b = (s1 >= 0) ? g_Y[(size_t)s1 * DIM + i] : 0.f;
        v[r] = w0 * a + w1 * b;
        sum += v[r];
    }

    __shared__ float red[256];
    red[tid] = sum;
    __syncthreads();
#pragma unroll
    for (int o = 128; o > 0; o >>= 1) {
        if (tid < o) red[tid] += red[tid + o];
        __syncthreads();
    }
    float mu = red[0] * (1.f / (float)DIM);
    __syncthreads();

    float sq = 0.f;
#pragma unroll
    for (int r = 0; r < 3; r++) { float d = v[r] - mu; sq += d * d; }
    red[tid] = sq;
    __syncthreads();
#pragma unroll
    for (int o = 128; o > 0; o >>= 1) {
        if (tid < o) red[tid] += red[tid + o];
        __syncthreads();
    }
    float rstd = rsqrtf(red[0] * (1.f / (float)DIM) + 1e-5f);

#pragma unroll
    for (int r = 0; r < 3; r++) {
        int i = r * 256 + tid;
        out[(size_t)t * DIM + i] = (v[r] - mu) * rstd * lnw[i] + lnb[i];
    }
}

// ---------------------------------------------------------------------------
// Launch
// ---------------------------------------------------------------------------
extern "C" void kernel_launch(void* const* d_in, const int* in_sizes, int n_in,
                              void* d_out, int out_size)
{
    const float* x   = (const float*)d_in[0];
    const float* wg  = (const float*)d_in[1];
    const float* w1  = (const float*)d_in[2];
    const float* b1  = (const float*)d_in[3];
    const float* w2  = (const float*)d_in[4];
    const float* b2  = (const float*)d_in[5];
    const float* lnw = (const float*)d_in[6];
    const float* lnb = (const float*)d_in[7];
    float* out = (float*)d_out;

    const int SMEM_BYTES = 3 * 8192 * 4;   // 98304
    cudaFuncSetAttribute(gemm_f16_kernel<KCH1, HID, true>,
                         cudaFuncAttributeMaxDynamicSharedMemorySize, SMEM_BYTES);
    cudaFuncSetAttribute(gemm_f16_kernel<KCH2, DIM, false>,
                         cudaFuncAttributeMaxDynamicSharedMemorySize, SMEM_BYTES);

    __half* w1f; cudaGetSymbolAddress((void**)&w1f, g_w1f);
    __half* w2f; cudaGetSymbolAddress((void**)&w2f, g_w2f);
    __half* xg;  cudaGetSymbolAddress((void**)&xg,  g_xg);
    __half* Hbuf; cudaGetSymbolAddress((void**)&Hbuf, g_H);
    float* Ybuf; cudaGetSymbolAddress((void**)&Ybuf, g_Y);

    zero_counts_kernel<<<1, 32>>>();
    router_kernel<<<N_TOK / 8, 256>>>(x, wg);
    assign_kernel<<<N_TOK / 256, 256>>>();

    wtransform_kernel<<<dim3((HID / 128) * KCH1, NEXP), 128>>>(w1, w1f, DIM, HID);
    wtransform_kernel<<<dim3((DIM / 128) * KCH2, NEXP), 128>>>(w2, w2f, HID, DIM);

    gather_frag_kernel<<<dim3(CAP / 16, NEXP), 256>>>(x);

    gemm_f16_kernel<KCH1, HID, true><<<dim3(HID / 128, MTILES, NEXP), 256, SMEM_BYTES>>>(
        xg, w1f, b1, Hbuf);
    gemm_f16_kernel<KCH2, DIM, false><<<dim3(DIM / 128, MTILES, NEXP), 256, SMEM_BYTES>>>(
        Hbuf, w2f, b2, Ybuf);

    combine_ln_kernel<<<N_TOK, 256>>>(lnw, lnb, out);
}

// round 10
// speedup vs baseline: 2.3083x; 1.0288x over previous
#include <cuda_runtime.h>
#include <cuda_fp16.h>
#include <math.h>
#include <stdint.h>

#define N_TOK 32768
#define DIM   768
#define HID   3072
#define NEXP  8
#define CAP   10240
#define MTILES (CAP / 128)          // 80
#define KCH1  (DIM / 64)            // 12
#define KCH2  (HID / 64)            // 48

// ---------------------------------------------------------------------------
// Scratch. Fragment-major fp16 blobs, 16KB each (1024 float4 units):
//  A-blob (128m x 64k):  unit q=(m16blk*4+ks)*32+t ; word j: row=m16*16+gid+8*(j&1),
//                        k=ks*16+tig*2+{0,1}+8*(j>>1)
//  B-blob (64k x 128n):  unit q=(ks*8+pp)*32+t ; word j: n=pp*16+8*(j>>1)+gid,
//                        k=ks*16+tig*2+{0,1}+8*(j&1)
// ---------------------------------------------------------------------------
__device__ int    g_cnt[NEXP];
__device__ int    g_route_e[N_TOK * 2];
__device__ float  g_route_w[N_TOK * 2];
__device__ int    g_tokidx[NEXP * CAP];
__device__ int    g_slot[N_TOK * 2];
__device__ __half g_xg [(size_t)NEXP * CAP * DIM];
__device__ __half g_w1f[(size_t)NEXP * DIM * HID];
__device__ __half g_w2f[(size_t)NEXP * HID * DIM];
__device__ __half g_H  [(size_t)NEXP * CAP * HID];
__device__ float  g_Y  [(size_t)NEXP * CAP * DIM];

// ---------------------------------------------------------------------------
// Helpers
// ---------------------------------------------------------------------------
__device__ __forceinline__ void cp16(void* dst, const void* src) {
    uint32_t d;
    asm("{ .reg .u64 t; cvta.to.shared.u64 t, %1; cvt.u32.u64 %0, t; }" : "=r"(d) : "l"(dst));
    asm volatile("cp.async.cg.shared.global [%0], [%1], 16;" :: "r"(d), "l"(src));
}
#define CP_COMMIT() asm volatile("cp.async.commit_group;" ::: "memory")
#define CP_WAIT1()  asm volatile("cp.async.wait_group 1;" ::: "memory")

#define MMA_F16(c, a, b) \
    asm volatile("mma.sync.aligned.m16n8k16.row.col.f32.f16.f16.f32 " \
        "{%0,%1,%2,%3}, {%4,%5,%6,%7}, {%8,%9}, {%0,%1,%2,%3};" \
        : "+f"((c)[0]), "+f"((c)[1]), "+f"((c)[2]), "+f"((c)[3]) \
        : "r"((a)[0]), "r"((a)[1]), "r"((a)[2]), "r"((a)[3]), \
          "r"((b)[0]), "r"((b)[1]))

// ---------------------------------------------------------------------------
// Kernel 0: zero counters
// ---------------------------------------------------------------------------
__global__ void zero_counts_kernel() {
    if (threadIdx.x < NEXP) g_cnt[threadIdx.x] = 0;
}

// ---------------------------------------------------------------------------
// Kernel 1: router (one warp per token, exact fp32)
// ---------------------------------------------------------------------------
__global__ __launch_bounds__(256) void router_kernel(
    const float* __restrict__ x, const float* __restrict__ wg)
{
    int warp = (blockIdx.x * blockDim.x + threadIdx.x) >> 5;
    int lane = threadIdx.x & 31;
    if (warp >= N_TOK) return;
    const float* xr = x + (size_t)warp * DIM;

    float acc[NEXP];
#pragma unroll
    for (int e = 0; e < NEXP; e++) acc[e] = 0.f;
    for (int j = lane; j < DIM; j += 32) {
        float xv = xr[j];
        const float* wr = wg + j * NEXP;
#pragma unroll
        for (int e = 0; e < NEXP; e++) acc[e] += xv * wr[e];
    }
#pragma unroll
    for (int e = 0; e < NEXP; e++) {
#pragma unroll
        for (int o = 16; o > 0; o >>= 1)
            acc[e] += __shfl_xor_sync(0xffffffffu, acc[e], o);
    }
    if (lane == 0) {
        int e0 = 0; float v0 = acc[0];
#pragma unroll
        for (int e = 1; e < NEXP; e++) if (acc[e] > v0) { v0 = acc[e]; e0 = e; }
        int e1 = -1; float v1 = -3.4e38f;
#pragma unroll
        for (int e = 0; e < NEXP; e++) if (e != e0 && acc[e] > v1) { v1 = acc[e]; e1 = e; }
        float ex = expf(v1 - v0);
        float s  = 1.f + ex;
        g_route_e[2 * warp + 0] = e0;  g_route_w[2 * warp + 0] = 1.f / s;
        g_route_e[2 * warp + 1] = e1;  g_route_w[2 * warp + 1] = ex / s;
    }
}

// ---------------------------------------------------------------------------
// Kernel 2: slot assignment
// ---------------------------------------------------------------------------
__global__ void assign_kernel() {
    int t = blockIdx.x * blockDim.x + threadIdx.x;
    if (t >= N_TOK) return;
#pragma unroll
    for (int k = 0; k < 2; k++) {
        int e = g_route_e[2 * t + k];
        int pos = atomicAdd(&g_cnt[e], 1);
        if (pos < CAP) {
            g_tokidx[e * CAP + pos] = t;
            g_slot[2 * t + k] = e * CAP + pos;
        } else {
            g_slot[2 * t + k] = -1;
        }
    }
}

// ---------------------------------------------------------------------------
// Kernel 3: weight -> fp16 B-blob transform
// ---------------------------------------------------------------------------
__global__ __launch_bounds__(128) void wtransform_kernel(
    const float* __restrict__ w, __half* __restrict__ out, int KD, int ND)
{
    const int nkc = KD / 64;
    const int e  = blockIdx.y;
    const int nt = blockIdx.x / nkc;
    const int kc = blockIdx.x % nkc;
    __shared__ float tile[64][132];

    const int tid = threadIdx.x;
    const float* src = w + ((size_t)e * KD + kc * 64) * ND + nt * 128;
#pragma unroll
    for (int u = tid; u < 2048; u += 128) {
        int r = u >> 5, c = (u & 31) * 4;
        float4 v = *(const float4*)(src + (size_t)r * ND + c);
        tile[r][c + 0] = v.x; tile[r][c + 1] = v.y;
        tile[r][c + 2] = v.z; tile[r][c + 3] = v.w;
    }
    __syncthreads();

    float4* dst = (float4*)(out + (((size_t)(e * (ND / 128) + nt) * nkc + kc) << 13));
#pragma unroll
    for (int u = tid; u < 1024; u += 128) {
        int t = u & 31, pp = (u >> 5) & 7, ks = u >> 8;
        int gid = t >> 2, tig = t & 3;
        __half2 h[4];
#pragma unroll
        for (int j = 0; j < 4; j++) {
            int n = pp * 16 + 8 * (j >> 1) + gid;
            int k = ks * 16 + tig * 2 + 8 * (j & 1);
            h[j] = __floats2half2_rn(tile[k][n], tile[k + 1][n]);
        }
        float4 v;
        v.x = __uint_as_float(*(uint32_t*)&h[0]);
        v.y = __uint_as_float(*(uint32_t*)&h[1]);
        v.z = __uint_as_float(*(uint32_t*)&h[2]);
        v.w = __uint_as_float(*(uint32_t*)&h[3]);
        dst[u] = v;
    }
}

// ---------------------------------------------------------------------------
// Kernel 4: gather routed tokens into fp16 A-blobs
// ---------------------------------------------------------------------------
__global__ __launch_bounds__(256) void gather_frag_kernel(const float* __restrict__ x) {
    const int e = blockIdx.y;
    const int Me = min(g_cnt[e], CAP);
    const int g16 = blockIdx.x;
    const int base = g16 * 16;
    if (base >= Me) return;

    __shared__ float rows[16][772];
    const int tid = threadIdx.x;

    for (int u = tid; u < 16 * 192; u += 256) {
        int r = u / 192, c = (u % 192) * 4;
        int pos = base + r;
        if (pos < Me) {
            int tok = g_tokidx[e * CAP + pos];
            float4 v = *(const float4*)(x + (size_t)tok * DIM + c);
            rows[r][c + 0] = v.x; rows[r][c + 1] = v.y;
            rows[r][c + 2] = v.z; rows[r][c + 3] = v.w;
        } else {
            rows[r][c + 0] = 0.f; rows[r][c + 1] = 0.f;
            rows[r][c + 2] = 0.f; rows[r][c + 3] = 0.f;
        }
    }
    __syncthreads();

    const int mtile = g16 >> 3, m16blk = g16 & 7;
    float4* outb = (float4*)g_xg;
    for (int u = tid; u < 1536; u += 256) {
        int kc = u >> 7, r = u & 127;
        int ks = r >> 5, t = r & 31;
        int gid = t >> 2, tig = t & 3;
        __half2 h[4];
#pragma unroll
        for (int j = 0; j < 4; j++) {
            int row = gid + 8 * (j & 1);
            int col = kc * 64 + ks * 16 + tig * 2 + 8 * (j >> 1);
            h[j] = __floats2half2_rn(rows[row][col], rows[row][col + 1]);
        }
        float4 v;
        v.x = __uint_as_float(*(uint32_t*)&h[0]);
        v.y = __uint_as_float(*(uint32_t*)&h[1]);
        v.z = __uint_as_float(*(uint32_t*)&h[2]);
        v.w = __uint_as_float(*(uint32_t*)&h[3]);
        outb[(((size_t)((e * MTILES + mtile) * KCH1 + kc)) << 10) + m16blk * 128 + ks * 32 + t] = v;
    }
}

// ---------------------------------------------------------------------------
// fp16 fragment-major GEMM. CTA 128x128, 4 warps (2x2), warp tile 64x64.
//   acc[4][8][4] = 128 regs. 128 threads -> 2 CTAs/SM without reg pressure.
//   Mainloop per warp-ks: 8 LDS.128 + 32 MMA (ratio 0.25 vs R9's 0.375).
// ---------------------------------------------------------------------------
template<int NKCH, int NDIM, bool EPI_FRAG>
__global__ __launch_bounds__(128, 2) void gemm_f16_kernel(
    const __half* __restrict__ Ablobs,
    const __half* __restrict__ Bblobs,
    const float* __restrict__ bias,
    void* __restrict__ Cout)
{
    const int e  = blockIdx.z;
    const int Me = min(g_cnt[e], CAP);
    const int m0 = blockIdx.y * 128;
    if (m0 >= Me) return;
    const int bx = blockIdx.x;

    extern __shared__ float smem[];           // 3 stages x 8192 floats (32KB)
    const int tid = threadIdx.x;
    const int wid = tid >> 5, lid = tid & 31;
    const int gid = lid >> 2, tig = lid & 3;
    const int wMblk = (wid >> 1) * 4;         // m16 block base (0 or 4)
    const int pbase = (wid & 1) * 4;          // B pair base (0 or 4)

    const float4* Ab = (const float4*)(Ablobs + (((size_t)(e * MTILES + blockIdx.y) * NKCH) << 13));
    const float4* Bb = (const float4*)(Bblobs + (((size_t)(e * (NDIM / 128) + bx) * NKCH) << 13));

    float acc[4][8][4];
#pragma unroll
    for (int mf = 0; mf < 4; mf++)
#pragma unroll
        for (int nf = 0; nf < 8; nf++)
#pragma unroll
            for (int q = 0; q < 4; q++) acc[mf][nf][q] = 0.f;

    auto issue = [&](int i) {
        float4* dst = (float4*)(smem + (i % 3) * 8192);
        const float4* a = Ab + ((size_t)i << 10);
        const float4* b = Bb + ((size_t)i << 10);
#pragma unroll
        for (int j = 0; j < 8; j++)
            cp16(dst + j * 128 + tid, a + j * 128 + tid);
#pragma unroll
        for (int j = 0; j < 8; j++)
            cp16(dst + 1024 + j * 128 + tid, b + j * 128 + tid);
        CP_COMMIT();
    };

    issue(0);
    issue(1);

    for (int i = 0; i < NKCH; i++) {
        CP_WAIT1();
        __syncthreads();
        if (i + 2 < NKCH) issue(i + 2); else CP_COMMIT();

        const float4* pA = (const float4*)(smem + (i % 3) * 8192);
        const float4* pB = pA + 1024;
#pragma unroll
        for (int ks = 0; ks < 4; ks++) {
            uint32_t a[4][4], b[8][2];
#pragma unroll
            for (int mf = 0; mf < 4; mf++) {
                float4 v = pA[((wMblk + mf) * 4 + ks) * 32 + lid];
                a[mf][0] = __float_as_uint(v.x);
                a[mf][1] = __float_as_uint(v.y);
                a[mf][2] = __float_as_uint(v.z);
                a[mf][3] = __float_as_uint(v.w);
            }
#pragma unroll
            for (int q = 0; q < 4; q++) {
                float4 v = pB[(ks * 8 + pbase + q) * 32 + lid];
                b[2 * q + 0][0] = __float_as_uint(v.x);
                b[2 * q + 0][1] = __float_as_uint(v.y);
                b[2 * q + 1][0] = __float_as_uint(v.z);
                b[2 * q + 1][1] = __float_as_uint(v.w);
            }
#pragma unroll
            for (int mf = 0; mf < 4; mf++)
#pragma unroll
                for (int nf = 0; nf < 8; nf++)
                    MMA_F16(acc[mf][nf], a[mf], b[nf]);
        }
    }

    const int warpM = (wid >> 1) * 64;        // 0 or 64
    const int warpN = (wid & 1) * 64;         // 0 or 64
    const int n0 = bx * 128;
    const float* bp = bias + (size_t)e * NDIM + n0 + warpN;

    if (EPI_FRAG) {
        // gelu -> fp16 H blobs (GEMM2 A layout), staged via smem (2 blobs = 32KB)
        __syncthreads();
#pragma unroll
        for (int mf = 0; mf < 4; mf++)
#pragma unroll
            for (int half = 0; half < 2; half++) {
                int m_local = warpM + mf * 16 + gid + half * 8;
                int m16blk = m_local >> 4, mm = m_local & 15;
                int gid_a = mm & 7, ja_lo = mm >> 3;
#pragma unroll
                for (int nf = 0; nf < 8; nf++) {
                    int n_local = warpN + nf * 8 + tig * 2;
                    float v0 = acc[mf][nf][half * 2 + 0] + bp[nf * 8 + tig * 2 + 0];
                    float v1 = acc[mf][nf][half * 2 + 1] + bp[nf * 8 + tig * 2 + 1];
                    v0 = 0.5f * v0 * (1.f + erff(v0 * 0.70710678118654752f));
                    v1 = 0.5f * v1 * (1.f + erff(v1 * 0.70710678118654752f));
                    __half2 hv = __floats2half2_rn(v0, v1);
                    int kc_l = n_local >> 6;
                    int kin  = n_local & 63;
                    int ks = kin >> 4, kk = kin & 15;
                    int ja_hi = kk >> 3, tig_a = (kk & 7) >> 1;
                    int t_a = gid_a * 4 + tig_a;
                    int tw = t_a ^ (((t_a >> 3) & 3) << 1);
                    int q = kc_l * 1024 + (m16blk * 4 + ks) * 32 + tw;
                    ((__half2*)smem)[q * 4 + (ja_lo + 2 * ja_hi)] = hv;
                }
            }
        __syncthreads();
        float4* dst = (float4*)((__half*)Cout +
            (((size_t)((e * MTILES + blockIdx.y) * KCH2 + bx * 2)) << 13));
        const float4* st = (const float4*)smem;
#pragma unroll
        for (int u = tid; u < 2048; u += 128) {
            int t = u & 31;
            int tw = t ^ (((t >> 3) & 3) << 1);
            dst[u] = st[(u & ~31) | tw];
        }
    } else {
        float* Cf = (float*)Cout;
#pragma unroll
        for (int mf = 0; mf < 4; mf++)
#pragma unroll
            for (int half = 0; half < 2; half++) {
                int m = m0 + warpM + mf * 16 + gid + half * 8;
                if (m >= Me) continue;
                float* Crow = Cf + (size_t)(e * CAP + m) * NDIM + n0 + warpN;
#pragma unroll
                for (int nf = 0; nf < 8; nf++) {
                    float2 o;
                    o.x = acc[mf][nf][half * 2 + 0] + bp[nf * 8 + tig * 2 + 0];
                    o.y = acc[mf][nf][half * 2 + 1] + bp[nf * 8 + tig * 2 + 1];
                    *(float2*)(Crow + nf * 8 + tig * 2) = o;
                }
            }
    }
}

// ---------------------------------------------------------------------------
// combine + LayerNorm
// ---------------------------------------------------------------------------
__global__ __launch_bounds__(256) void combine_ln_kernel(
    const float* __restrict__ lnw,
    const float* __restrict__ lnb,
    float* __restrict__ out)
{
    const int t   = blockIdx.x;
    const int tid = threadIdx.x;
    const int s0  = g_slot[2 * t + 0];
    const int s1  = g_slot[2 * t + 1];
    const float w0 = g_route_w[2 * t + 0];
    const float w1 = g_route_w[2 * t + 1];

    float v[3];
    float sum = 0.f;
#pragma unroll
    for (int r = 0; r < 3; r++) {
        int i = r * 256 + tid;
        float a = (s0 >= 0) ? g_Y[(size_t)s0 * DIM + i] : 0.f;
        float b = (s1 >= 0) ? g_Y[(size_t)s1 * DIM + i] : 0.f;
        v[r] = w0 * a + w1 * b;
        sum += v[r];
    }

    __shared__ float red[256];
    red[tid] = sum;
    __syncthreads();
#pragma unroll
    for (int o = 128; o > 0; o >>= 1) {
        if (tid < o) red[tid] += red[tid + o];
        __syncthreads();
    }
    float mu = red[0] * (1.f / (float)DIM);
    __syncthreads();

    float sq = 0.f;
#pragma unroll
    for (int r = 0; r < 3; r++) { float d = v[r] - mu; sq += d * d; }
    red[tid] = sq;
    __syncthreads();
#pragma unroll
    for (int o = 128; o > 0; o >>= 1) {
        if (tid < o) red[tid] += red[tid + o];
        __syncthreads();
    }
    float rstd = rsqrtf(red[0] * (1.f / (float)DIM) + 1e-5f);

#pragma unroll
    for (int r = 0; r < 3; r++) {
        int i = r * 256 + tid;
        out[(size_t)t * DIM + i] = (v[r] - mu) * rstd * lnw[i] + lnb[i];
    }
}

// ---------------------------------------------------------------------------
// Launch
// ---------------------------------------------------------------------------
extern "C" void kernel_launch(void* const* d_in, const int* in_sizes, int n_in,
                              void* d_out, int out_size)
{
    const float* x   = (const float*)d_in[0];
    const float* wg  = (const float*)d_in[1];
    const float* w1  = (const float*)d_in[2];
    const float* b1  = (const float*)d_in[3];
    const float* w2  = (const float*)d_in[4];
    const float* b2  = (const float*)d_in[5];
    const float* lnw = (const float*)d_in[6];
    const float* lnb = (const float*)d_in[7];
    float* out = (float*)d_out;

    const int SMEM_BYTES = 3 * 8192 * 4;   // 98304
    cudaFuncSetAttribute(gemm_f16_kernel<KCH1, HID, true>,
                         cudaFuncAttributeMaxDynamicSharedMemorySize, SMEM_BYTES);
    cudaFuncSetAttribute(gemm_f16_kernel<KCH2, DIM, false>,
                         cudaFuncAttributeMaxDynamicSharedMemorySize, SMEM_BYTES);

    __half* w1f; cudaGetSymbolAddress((void**)&w1f, g_w1f);
    __half* w2f; cudaGetSymbolAddress((void**)&w2f, g_w2f);
    __half* xg;  cudaGetSymbolAddress((void**)&xg,  g_xg);
    __half* Hbuf; cudaGetSymbolAddress((void**)&Hbuf, g_H);
    float* Ybuf; cudaGetSymbolAddress((void**)&Ybuf, g_Y);

    zero_counts_kernel<<<1, 32>>>();
    router_kernel<<<N_TOK / 8, 256>>>(x, wg);
    assign_kernel<<<N_TOK / 256, 256>>>();

    wtransform_kernel<<<dim3((HID / 128) * KCH1, NEXP), 128>>>(w1, w1f, DIM, HID);
    wtransform_kernel<<<dim3((DIM / 128) * KCH2, NEXP), 128>>>(w2, w2f, HID, DIM);

    gather_frag_kernel<<<dim3(CAP / 16, NEXP), 256>>>(x);

    gemm_f16_kernel<KCH1, HID, true><<<dim3(HID / 128, MTILES, NEXP), 128, SMEM_BYTES>>>(
        xg, w1f, b1, Hbuf);
    gemm_f16_kernel<KCH2, DIM, false><<<dim3(DIM / 128, MTILES, NEXP), 128, SMEM_BYTES>>>(
        Hbuf, w2f, b2, Ybuf);

    combine_ln_kernel<<<N_TOK, 256>>>(lnw, lnb, out);
}

// round 11
// speedup vs baseline: 2.3924x; 1.0364x over previous
#include <cuda_runtime.h>
#include <cuda_fp16.h>
#include <math.h>
#include <stdint.h>

#define N_TOK 32768
#define DIM   768
#define HID   3072
#define NEXP  8
#define CAP   10240
#define MTILES (CAP / 128)          // 80
#define KCH1  (DIM / 64)            // 12
#define KCH2  (HID / 64)            // 48

// ---------------------------------------------------------------------------
// Scratch. Fragment-major fp16 blobs, 16KB each (1024 float4 units):
//  A-blob (128m x 64k):  unit q=(m16blk*4+ks)*32+t ; word j: row=m16*16+gid+8*(j&1),
//                        k=ks*16+tig*2+{0,1}+8*(j>>1)
//  B-blob (64k x 128n):  unit q=(ks*8+pp)*32+t ; word j: n=pp*16+8*(j>>1)+gid,
//                        k=ks*16+tig*2+{0,1}+8*(j&1)
// ---------------------------------------------------------------------------
__device__ int    g_cnt[NEXP];
__device__ int    g_route_e[N_TOK * 2];
__device__ float  g_route_w[N_TOK * 2];
__device__ int    g_tokidx[NEXP * CAP];
__device__ int    g_slot[N_TOK * 2];
__device__ __half g_xg [(size_t)NEXP * CAP * DIM];
__device__ __half g_w1f[(size_t)NEXP * DIM * HID];
__device__ __half g_w2f[(size_t)NEXP * HID * DIM];
__device__ __half g_H  [(size_t)NEXP * CAP * HID];
__device__ float  g_Y  [(size_t)NEXP * CAP * DIM];

// ---------------------------------------------------------------------------
// Helpers
// ---------------------------------------------------------------------------
__device__ __forceinline__ void cp16(void* dst, const void* src) {
    uint32_t d;
    asm("{ .reg .u64 t; cvta.to.shared.u64 t, %1; cvt.u32.u64 %0, t; }" : "=r"(d) : "l"(dst));
    asm volatile("cp.async.cg.shared.global [%0], [%1], 16;" :: "r"(d), "l"(src));
}
#define CP_COMMIT() asm volatile("cp.async.commit_group;" ::: "memory")
#define CP_WAIT1()  asm volatile("cp.async.wait_group 1;" ::: "memory")

#define MMA_F16(c, a, b) \
    asm volatile("mma.sync.aligned.m16n8k16.row.col.f32.f16.f16.f32 " \
        "{%0,%1,%2,%3}, {%4,%5,%6,%7}, {%8,%9}, {%0,%1,%2,%3};" \
        : "+f"((c)[0]), "+f"((c)[1]), "+f"((c)[2]), "+f"((c)[3]) \
        : "r"((a)[0]), "r"((a)[1]), "r"((a)[2]), "r"((a)[3]), \
          "r"((b)[0]), "r"((b)[1]))

// ---------------------------------------------------------------------------
// Kernel 0: zero counters
// ---------------------------------------------------------------------------
__global__ void zero_counts_kernel() {
    if (threadIdx.x < NEXP) g_cnt[threadIdx.x] = 0;
}

// ---------------------------------------------------------------------------
// Kernel 1: router (one warp per token, exact fp32)
// ---------------------------------------------------------------------------
__global__ __launch_bounds__(256) void router_kernel(
    const float* __restrict__ x, const float* __restrict__ wg)
{
    int warp = (blockIdx.x * blockDim.x + threadIdx.x) >> 5;
    int lane = threadIdx.x & 31;
    if (warp >= N_TOK) return;
    const float* xr = x + (size_t)warp * DIM;

    float acc[NEXP];
#pragma unroll
    for (int e = 0; e < NEXP; e++) acc[e] = 0.f;
    for (int j = lane; j < DIM; j += 32) {
        float xv = xr[j];
        const float* wr = wg + j * NEXP;
#pragma unroll
        for (int e = 0; e < NEXP; e++) acc[e] += xv * wr[e];
    }
#pragma unroll
    for (int e = 0; e < NEXP; e++) {
#pragma unroll
        for (int o = 16; o > 0; o >>= 1)
            acc[e] += __shfl_xor_sync(0xffffffffu, acc[e], o);
    }
    if (lane == 0) {
        int e0 = 0; float v0 = acc[0];
#pragma unroll
        for (int e = 1; e < NEXP; e++) if (acc[e] > v0) { v0 = acc[e]; e0 = e; }
        int e1 = -1; float v1 = -3.4e38f;
#pragma unroll
        for (int e = 0; e < NEXP; e++) if (e != e0 && acc[e] > v1) { v1 = acc[e]; e1 = e; }
        float ex = expf(v1 - v0);
        float s  = 1.f + ex;
        g_route_e[2 * warp + 0] = e0;  g_route_w[2 * warp + 0] = 1.f / s;
        g_route_e[2 * warp + 1] = e1;  g_route_w[2 * warp + 1] = ex / s;
    }
}

// ---------------------------------------------------------------------------
// Kernel 2: slot assignment
// ---------------------------------------------------------------------------
__global__ void assign_kernel() {
    int t = blockIdx.x * blockDim.x + threadIdx.x;
    if (t >= N_TOK) return;
#pragma unroll
    for (int k = 0; k < 2; k++) {
        int e = g_route_e[2 * t + k];
        int pos = atomicAdd(&g_cnt[e], 1);
        if (pos < CAP) {
            g_tokidx[e * CAP + pos] = t;
            g_slot[2 * t + k] = e * CAP + pos;
        } else {
            g_slot[2 * t + k] = -1;
        }
    }
}

// ---------------------------------------------------------------------------
// Kernel 3: weight -> fp16 B-blob transform
// ---------------------------------------------------------------------------
__global__ __launch_bounds__(128) void wtransform_kernel(
    const float* __restrict__ w, __half* __restrict__ out, int KD, int ND)
{
    const int nkc = KD / 64;
    const int e  = blockIdx.y;
    const int nt = blockIdx.x / nkc;
    const int kc = blockIdx.x % nkc;
    __shared__ float tile[64][132];

    const int tid = threadIdx.x;
    const float* src = w + ((size_t)e * KD + kc * 64) * ND + nt * 128;
#pragma unroll
    for (int u = tid; u < 2048; u += 128) {
        int r = u >> 5, c = (u & 31) * 4;
        float4 v = *(const float4*)(src + (size_t)r * ND + c);
        tile[r][c + 0] = v.x; tile[r][c + 1] = v.y;
        tile[r][c + 2] = v.z; tile[r][c + 3] = v.w;
    }
    __syncthreads();

    float4* dst = (float4*)(out + (((size_t)(e * (ND / 128) + nt) * nkc + kc) << 13));
#pragma unroll
    for (int u = tid; u < 1024; u += 128) {
        int t = u & 31, pp = (u >> 5) & 7, ks = u >> 8;
        int gid = t >> 2, tig = t & 3;
        __half2 h[4];
#pragma unroll
        for (int j = 0; j < 4; j++) {
            int n = pp * 16 + 8 * (j >> 1) + gid;
            int k = ks * 16 + tig * 2 + 8 * (j & 1);
            h[j] = __floats2half2_rn(tile[k][n], tile[k + 1][n]);
        }
        float4 v;
        v.x = __uint_as_float(*(uint32_t*)&h[0]);
        v.y = __uint_as_float(*(uint32_t*)&h[1]);
        v.z = __uint_as_float(*(uint32_t*)&h[2]);
        v.w = __uint_as_float(*(uint32_t*)&h[3]);
        dst[u] = v;
    }
}

// ---------------------------------------------------------------------------
// Kernel 4: gather routed tokens into fp16 A-blobs
// ---------------------------------------------------------------------------
__global__ __launch_bounds__(256) void gather_frag_kernel(const float* __restrict__ x) {
    const int e = blockIdx.y;
    const int Me = min(g_cnt[e], CAP);
    const int g16 = blockIdx.x;
    const int base = g16 * 16;
    if (base >= Me) return;

    __shared__ float rows[16][772];
    const int tid = threadIdx.x;

    for (int u = tid; u < 16 * 192; u += 256) {
        int r = u / 192, c = (u % 192) * 4;
        int pos = base + r;
        if (pos < Me) {
            int tok = g_tokidx[e * CAP + pos];
            float4 v = *(const float4*)(x + (size_t)tok * DIM + c);
            rows[r][c + 0] = v.x; rows[r][c + 1] = v.y;
            rows[r][c + 2] = v.z; rows[r][c + 3] = v.w;
        } else {
            rows[r][c + 0] = 0.f; rows[r][c + 1] = 0.f;
            rows[r][c + 2] = 0.f; rows[r][c + 3] = 0.f;
        }
    }
    __syncthreads();

    const int mtile = g16 >> 3, m16blk = g16 & 7;
    float4* outb = (float4*)g_xg;
    for (int u = tid; u < 1536; u += 256) {
        int kc = u >> 7, r = u & 127;
        int ks = r >> 5, t = r & 31;
        int gid = t >> 2, tig = t & 3;
        __half2 h[4];
#pragma unroll
        for (int j = 0; j < 4; j++) {
            int row = gid + 8 * (j & 1);
            int col = kc * 64 + ks * 16 + tig * 2 + 8 * (j >> 1);
            h[j] = __floats2half2_rn(rows[row][col], rows[row][col + 1]);
        }
        float4 v;
        v.x = __uint_as_float(*(uint32_t*)&h[0]);
        v.y = __uint_as_float(*(uint32_t*)&h[1]);
        v.z = __uint_as_float(*(uint32_t*)&h[2]);
        v.w = __uint_as_float(*(uint32_t*)&h[3]);
        outb[(((size_t)((e * MTILES + mtile) * KCH1 + kc)) << 10) + m16blk * 128 + ks * 32 + t] = v;
    }
}

// ---------------------------------------------------------------------------
// fp16 fragment-major GEMM. CTA 128x128, 4 warps (2x2), warp tile 64x64.
//   Mainloop: prefetch cp.asyncs INTERLEAVED into the ks loop so MMAs start
//   immediately after the chunk barrier (tensor pipe stays fed).
// ---------------------------------------------------------------------------
template<int NKCH, int NDIM, bool EPI_FRAG>
__global__ __launch_bounds__(128, 2) void gemm_f16_kernel(
    const __half* __restrict__ Ablobs,
    const __half* __restrict__ Bblobs,
    const float* __restrict__ bias,
    void* __restrict__ Cout)
{
    const int e  = blockIdx.z;
    const int Me = min(g_cnt[e], CAP);
    const int m0 = blockIdx.y * 128;
    if (m0 >= Me) return;
    const int bx = blockIdx.x;

    extern __shared__ float smem[];           // 3 stages x 8192 floats (32KB)
    const int tid = threadIdx.x;
    const int wid = tid >> 5, lid = tid & 31;
    const int gid = lid >> 2, tig = lid & 3;
    const int wMblk = (wid >> 1) * 4;         // m16 block base (0 or 4)
    const int pbase = (wid & 1) * 4;          // B pair base (0 or 4)

    const float4* Ab = (const float4*)(Ablobs + (((size_t)(e * MTILES + blockIdx.y) * NKCH) << 13));
    const float4* Bb = (const float4*)(Bblobs + (((size_t)(e * (NDIM / 128) + bx) * NKCH) << 13));

    float acc[4][8][4];
#pragma unroll
    for (int mf = 0; mf < 4; mf++)
#pragma unroll
        for (int nf = 0; nf < 8; nf++)
#pragma unroll
            for (int q = 0; q < 4; q++) acc[mf][nf][q] = 0.f;

    // full-chunk issue (prologue only)
    auto issue_all = [&](int i) {
        float4* dst = (float4*)(smem + (i % 3) * 8192);
        const float4* a = Ab + ((size_t)i << 10);
        const float4* b = Bb + ((size_t)i << 10);
#pragma unroll
        for (int j = 0; j < 8; j++)
            cp16(dst + j * 128 + tid, a + j * 128 + tid);
#pragma unroll
        for (int j = 0; j < 8; j++)
            cp16(dst + 1024 + j * 128 + tid, b + j * 128 + tid);
        CP_COMMIT();
    };

    issue_all(0);
    issue_all(1);

    for (int i = 0; i < NKCH; i++) {
        CP_WAIT1();                 // chunk i resident
        __syncthreads();            // + all warps done with chunk i-1 buffer

        const bool pf = (i + 2 < NKCH);
        float4* pdst = (float4*)(smem + ((i + 2) % 3) * 8192);
        const float4* pa = Ab + ((size_t)(i + 2) << 10);
        const float4* pb = Bb + ((size_t)(i + 2) << 10);

        const float4* pA = (const float4*)(smem + (i % 3) * 8192);
        const float4* pB = pA + 1024;
#pragma unroll
        for (int ks = 0; ks < 4; ks++) {
            uint32_t a[4][4], b[8][2];
#pragma unroll
            for (int mf = 0; mf < 4; mf++) {
                float4 v = pA[((wMblk + mf) * 4 + ks) * 32 + lid];
                a[mf][0] = __float_as_uint(v.x);
                a[mf][1] = __float_as_uint(v.y);
                a[mf][2] = __float_as_uint(v.z);
                a[mf][3] = __float_as_uint(v.w);
            }
#pragma unroll
            for (int q = 0; q < 4; q++) {
                float4 v = pB[(ks * 8 + pbase + q) * 32 + lid];
                b[2 * q + 0][0] = __float_as_uint(v.x);
                b[2 * q + 0][1] = __float_as_uint(v.y);
                b[2 * q + 1][0] = __float_as_uint(v.z);
                b[2 * q + 1][1] = __float_as_uint(v.w);
            }
            // interleaved prefetch: 4 cp.asyncs of chunk i+2 per ks step
            if (pf) {
#pragma unroll
                for (int j = ks * 4; j < ks * 4 + 4; j++) {
                    if (j < 8) cp16(pdst + j * 128 + tid, pa + j * 128 + tid);
                    else       cp16(pdst + 1024 + (j - 8) * 128 + tid,
                                    pb + (j - 8) * 128 + tid);
                }
            }
#pragma unroll
            for (int mf = 0; mf < 4; mf++)
#pragma unroll
                for (int nf = 0; nf < 8; nf++)
                    MMA_F16(acc[mf][nf], a[mf], b[nf]);
        }
        CP_COMMIT();               // one group per chunk (empty on tail iters)
    }

    const int warpM = (wid >> 1) * 64;        // 0 or 64
    const int warpN = (wid & 1) * 64;         // 0 or 64
    const int n0 = bx * 128;
    const float* bp = bias + (size_t)e * NDIM + n0 + warpN;

    if (EPI_FRAG) {
        // gelu -> fp16 H blobs (GEMM2 A layout), staged via smem (2 blobs = 32KB)
        __syncthreads();
#pragma unroll
        for (int mf = 0; mf < 4; mf++)
#pragma unroll
            for (int half = 0; half < 2; half++) {
                int m_local = warpM + mf * 16 + gid + half * 8;
                int m16blk = m_local >> 4, mm = m_local & 15;
                int gid_a = mm & 7, ja_lo = mm >> 3;
#pragma unroll
                for (int nf = 0; nf < 8; nf++) {
                    int n_local = warpN + nf * 8 + tig * 2;
                    float v0 = acc[mf][nf][half * 2 + 0] + bp[nf * 8 + tig * 2 + 0];
                    float v1 = acc[mf][nf][half * 2 + 1] + bp[nf * 8 + tig * 2 + 1];
                    v0 = 0.5f * v0 * (1.f + erff(v0 * 0.70710678118654752f));
                    v1 = 0.5f * v1 * (1.f + erff(v1 * 0.70710678118654752f));
                    __half2 hv = __floats2half2_rn(v0, v1);
                    int kc_l = n_local >> 6;
                    int kin  = n_local & 63;
                    int ks = kin >> 4, kk = kin & 15;
                    int ja_hi = kk >> 3, tig_a = (kk & 7) >> 1;
                    int t_a = gid_a * 4 + tig_a;
                    int tw = t_a ^ (((t_a >> 3) & 3) << 1);
                    int q = kc_l * 1024 + (m16blk * 4 + ks) * 32 + tw;
                    ((__half2*)smem)[q * 4 + (ja_lo + 2 * ja_hi)] = hv;
                }
            }
        __syncthreads();
        float4* dst = (float4*)((__half*)Cout +
            (((size_t)((e * MTILES + blockIdx.y) * KCH2 + bx * 2)) << 13));
        const float4* st = (const float4*)smem;
#pragma unroll
        for (int u = tid; u < 2048; u += 128) {
            int t = u & 31;
            int tw = t ^ (((t >> 3) & 3) << 1);
            dst[u] = st[(u & ~31) | tw];
        }
    } else {
        float* Cf = (float*)Cout;
#pragma unroll
        for (int mf = 0; mf < 4; mf++)
#pragma unroll
            for (int half = 0; half < 2; half++) {
                int m = m0 + warpM + mf * 16 + gid + half * 8;
                if (m >= Me) continue;
                float* Crow = Cf + (size_t)(e * CAP + m) * NDIM + n0 + warpN;
#pragma unroll
                for (int nf = 0; nf < 8; nf++) {
                    float2 o;
                    o.x = acc[mf][nf][half * 2 + 0] + bp[nf * 8 + tig * 2 + 0];
                    o.y = acc[mf][nf][half * 2 + 1] + bp[nf * 8 + tig * 2 + 1];
                    *(float2*)(Crow + nf * 8 + tig * 2) = o;
                }
            }
    }
}

// ---------------------------------------------------------------------------
// combine + LayerNorm
// ---------------------------------------------------------------------------
__global__ __launch_bounds__(256) void combine_ln_kernel(
    const float* __restrict__ lnw,
    const float* __restrict__ lnb,
    float* __restrict__ out)
{
    const int t   = blockIdx.x;
    const int tid = threadIdx.x;
    const int s0  = g_slot[2 * t + 0];
    const int s1  = g_slot[2 * t + 1];
    const float w0 = g_route_w[2 * t + 0];
    const float w1 = g_route_w[2 * t + 1];

    float v[3];
    float sum = 0.f;
#pragma unroll
    for (int r = 0; r < 3; r++) {
        int i = r * 256 + tid;
        float a = (s0 >= 0) ? g_Y[(size_t)s0 * DIM + i] : 0.f;
        float b = (s1 >= 0) ? g_Y[(size_t)s1 * DIM + i] : 0.f;
        v[r] = w0 * a + w1 * b;
        sum += v[r];
    }

    __shared__ float red[256];
    red[tid] = sum;
    __syncthreads();
#pragma unroll
    for (int o = 128; o > 0; o >>= 1) {
        if (tid < o) red[tid] += red[tid + o];
        __syncthreads();
    }
    float mu = red[0] * (1.f / (float)DIM);
    __syncthreads();

    float sq = 0.f;
#pragma unroll
    for (int r = 0; r < 3; r++) { float d = v[r] - mu; sq += d * d; }
    red[tid] = sq;
    __syncthreads();
#pragma unroll
    for (int o = 128; o > 0; o >>= 1) {
        if (tid < o) red[tid] += red[tid + o];
        __syncthreads();
    }
    float rstd = rsqrtf(red[0] * (1.f / (float)DIM) + 1e-5f);

#pragma unroll
    for (int r = 0; r < 3; r++) {
        int i = r * 256 + tid;
        out[(size_t)t * DIM + i] = (v[r] - mu) * rstd * lnw[i] + lnb[i];
    }
}

// ---------------------------------------------------------------------------
// Launch
// ---------------------------------------------------------------------------
extern "C" void kernel_launch(void* const* d_in, const int* in_sizes, int n_in,
                              void* d_out, int out_size)
{
    const float* x   = (const float*)d_in[0];
    const float* wg  = (const float*)d_in[1];
    const float* w1  = (const float*)d_in[2];
    const float* b1  = (const float*)d_in[3];
    const float* w2  = (const float*)d_in[4];
    const float* b2  = (const float*)d_in[5];
    const float* lnw = (const float*)d_in[6];
    const float* lnb = (const float*)d_in[7];
    float* out = (float*)d_out;

    const int SMEM_BYTES = 3 * 8192 * 4;   // 98304
    cudaFuncSetAttribute(gemm_f16_kernel<KCH1, HID, true>,
                         cudaFuncAttributeMaxDynamicSharedMemorySize, SMEM_BYTES);
    cudaFuncSetAttribute(gemm_f16_kernel<KCH2, DIM, false>,
                         cudaFuncAttributeMaxDynamicSharedMemorySize, SMEM_BYTES);

    __half* w1f; cudaGetSymbolAddress((void**)&w1f, g_w1f);
    __half* w2f; cudaGetSymbolAddress((void**)&w2f, g_w2f);
    __half* xg;  cudaGetSymbolAddress((void**)&xg,  g_xg);
    __half* Hbuf; cudaGetSymbolAddress((void**)&Hbuf, g_H);
    float* Ybuf; cudaGetSymbolAddress((void**)&Ybuf, g_Y);

    zero_counts_kernel<<<1, 32>>>();
    router_kernel<<<N_TOK / 8, 256>>>(x, wg);
    assign_kernel<<<N_TOK / 256, 256>>>();

    wtransform_kernel<<<dim3((HID / 128) * KCH1, NEXP), 128>>>(w1, w1f, DIM, HID);
    wtransform_kernel<<<dim3((DIM / 128) * KCH2, NEXP), 128>>>(w2, w2f, HID, DIM);

    gather_frag_kernel<<<dim3(CAP / 16, NEXP), 256>>>(x);

    gemm_f16_kernel<KCH1, HID, true><<<dim3(HID / 128, MTILES, NEXP), 128, SMEM_BYTES>>>(
        xg, w1f, b1, Hbuf);
    gemm_f16_kernel<KCH2, DIM, false><<<dim3(DIM / 128, MTILES, NEXP), 128, SMEM_BYTES>>>(
        Hbuf, w2f, b2, Ybuf);

    combine_ln_kernel<<<N_TOK, 256>>>(lnw, lnb, out);
}

// round 12
// speedup vs baseline: 2.4054x; 1.0055x over previous
#include <cuda_runtime.h>
#include <cuda_fp16.h>
#include <math.h>
#include <stdint.h>

#define N_TOK 32768
#define DIM   768
#define HID   3072
#define NEXP  8
#define CAP   10240
#define MTILES (CAP / 128)          // 80
#define KCH1  (DIM / 64)            // 12
#define KCH2  (HID / 64)            // 48

// ---------------------------------------------------------------------------
// Scratch. Fragment-major fp16 blobs, 16KB each (1024 float4 units).
// ---------------------------------------------------------------------------
__device__ int    g_cnt[NEXP];
__device__ int    g_route_e[N_TOK * 2];
__device__ float  g_route_w[N_TOK * 2];
__device__ int    g_tokidx[NEXP * CAP];
__device__ int    g_slot[N_TOK * 2];
__device__ __half g_xg [(size_t)NEXP * CAP * DIM];
__device__ __half g_w1f[(size_t)NEXP * DIM * HID];
__device__ __half g_w2f[(size_t)NEXP * HID * DIM];
__device__ __half g_H  [(size_t)NEXP * CAP * HID];
__device__ float  g_Y  [(size_t)NEXP * CAP * DIM];

// ---------------------------------------------------------------------------
// Helpers
// ---------------------------------------------------------------------------
__device__ __forceinline__ void cp16(void* dst, const void* src) {
    uint32_t d;
    asm("{ .reg .u64 t; cvta.to.shared.u64 t, %1; cvt.u32.u64 %0, t; }" : "=r"(d) : "l"(dst));
    asm volatile("cp.async.cg.shared.global [%0], [%1], 16;" :: "r"(d), "l"(src));
}
#define CP_COMMIT() asm volatile("cp.async.commit_group;" ::: "memory")
#define CP_WAIT1()  asm volatile("cp.async.wait_group 1;" ::: "memory")

#define MMA_F16(c, a, b) \
    asm volatile("mma.sync.aligned.m16n8k16.row.col.f32.f16.f16.f32 " \
        "{%0,%1,%2,%3}, {%4,%5,%6,%7}, {%8,%9}, {%0,%1,%2,%3};" \
        : "+f"((c)[0]), "+f"((c)[1]), "+f"((c)[2]), "+f"((c)[3]) \
        : "r"((a)[0]), "r"((a)[1]), "r"((a)[2]), "r"((a)[3]), \
          "r"((b)[0]), "r"((b)[1]))

// ---------------------------------------------------------------------------
// Kernel 0: PREP = zero counters + router + both weight->blob transforms.
//   blocks [0, 4096):      router, 8 tokens per block (1 warp/token);
//                          block 0 also zeroes g_cnt.
//   blocks [4096, 6400):   w1 -> g_w1f blob transform (288 blobs/expert).
//   blocks [6400, 8704):   w2 -> g_w2f blob transform.
// ---------------------------------------------------------------------------
__global__ __launch_bounds__(256) void prep_kernel(
    const float* __restrict__ x,  const float* __restrict__ wg,
    const float* __restrict__ w1, const float* __restrict__ w2)
{
    __shared__ float tile[64][132];
    const int b = blockIdx.x;
    const int tid = threadIdx.x;

    if (b < 4096) {
        // ---- router (+ counter zeroing from block 0) ----
        if (b == 0 && tid < NEXP) g_cnt[tid] = 0;
        int warp = b * 8 + (tid >> 5);
        int lane = tid & 31;
        const float* xr = x + (size_t)warp * DIM;

        float acc[NEXP];
#pragma unroll
        for (int e = 0; e < NEXP; e++) acc[e] = 0.f;
        for (int j = lane; j < DIM; j += 32) {
            float xv = xr[j];
            const float* wr = wg + j * NEXP;
#pragma unroll
            for (int e = 0; e < NEXP; e++) acc[e] += xv * wr[e];
        }
#pragma unroll
        for (int e = 0; e < NEXP; e++) {
#pragma unroll
            for (int o = 16; o > 0; o >>= 1)
                acc[e] += __shfl_xor_sync(0xffffffffu, acc[e], o);
        }
        if (lane == 0) {
            int e0 = 0; float v0 = acc[0];
#pragma unroll
            for (int e = 1; e < NEXP; e++) if (acc[e] > v0) { v0 = acc[e]; e0 = e; }
            int e1 = -1; float v1 = -3.4e38f;
#pragma unroll
            for (int e = 0; e < NEXP; e++) if (e != e0 && acc[e] > v1) { v1 = acc[e]; e1 = e; }
            float ex = expf(v1 - v0);
            float s  = 1.f + ex;
            g_route_e[2 * warp + 0] = e0;  g_route_w[2 * warp + 0] = 1.f / s;
            g_route_e[2 * warp + 1] = e1;  g_route_w[2 * warp + 1] = ex / s;
        }
        return;
    }

    // ---- weight -> fp16 B-blob transform ----
    int wb = b - 4096;
    const float* w;
    __half* out;
    int KD, nkc;
    size_t ndiv;     // ND/128
    if (wb < 2304) { w = w1; out = g_w1f; KD = DIM; nkc = 12; ndiv = HID / 128; }
    else           { wb -= 2304; w = w2; out = g_w2f; KD = HID; nkc = 48; ndiv = DIM / 128; }
    const int ND = (int)(ndiv * 128);
    const int e  = wb / 288;
    const int r  = wb % 288;
    const int nt = r / nkc;
    const int kc = r % nkc;

    const float* src = w + ((size_t)e * KD + kc * 64) * ND + nt * 128;
#pragma unroll
    for (int u = tid; u < 2048; u += 256) {
        int rr = u >> 5, c = (u & 31) * 4;
        float4 v = *(const float4*)(src + (size_t)rr * ND + c);
        tile[rr][c + 0] = v.x; tile[rr][c + 1] = v.y;
        tile[rr][c + 2] = v.z; tile[rr][c + 3] = v.w;
    }
    __syncthreads();

    float4* dst = (float4*)(out + (((size_t)(e * ndiv + nt) * nkc + kc) << 13));
#pragma unroll
    for (int u = tid; u < 1024; u += 256) {
        int t = u & 31, pp = (u >> 5) & 7, ks = u >> 8;
        int gid = t >> 2, tig = t & 3;
        __half2 h[4];
#pragma unroll
        for (int j = 0; j < 4; j++) {
            int n = pp * 16 + 8 * (j >> 1) + gid;
            int k = ks * 16 + tig * 2 + 8 * (j & 1);
            h[j] = __floats2half2_rn(tile[k][n], tile[k + 1][n]);
        }
        float4 v;
        v.x = __uint_as_float(*(uint32_t*)&h[0]);
        v.y = __uint_as_float(*(uint32_t*)&h[1]);
        v.z = __uint_as_float(*(uint32_t*)&h[2]);
        v.w = __uint_as_float(*(uint32_t*)&h[3]);
        dst[u] = v;
    }
}

// ---------------------------------------------------------------------------
// Kernel 1: slot assignment
// ---------------------------------------------------------------------------
__global__ void assign_kernel() {
    int t = blockIdx.x * blockDim.x + threadIdx.x;
    if (t >= N_TOK) return;
#pragma unroll
    for (int k = 0; k < 2; k++) {
        int e = g_route_e[2 * t + k];
        int pos = atomicAdd(&g_cnt[e], 1);
        if (pos < CAP) {
            g_tokidx[e * CAP + pos] = t;
            g_slot[2 * t + k] = e * CAP + pos;
        } else {
            g_slot[2 * t + k] = -1;
        }
    }
}

// ---------------------------------------------------------------------------
// Kernel 2: gather routed tokens into fp16 A-blobs
// ---------------------------------------------------------------------------
__global__ __launch_bounds__(256) void gather_frag_kernel(const float* __restrict__ x) {
    const int e = blockIdx.y;
    const int Me = min(g_cnt[e], CAP);
    const int g16 = blockIdx.x;
    const int base = g16 * 16;
    if (base >= Me) return;

    __shared__ float rows[16][772];
    const int tid = threadIdx.x;

    for (int u = tid; u < 16 * 192; u += 256) {
        int r = u / 192, c = (u % 192) * 4;
        int pos = base + r;
        if (pos < Me) {
            int tok = g_tokidx[e * CAP + pos];
            float4 v = *(const float4*)(x + (size_t)tok * DIM + c);
            rows[r][c + 0] = v.x; rows[r][c + 1] = v.y;
            rows[r][c + 2] = v.z; rows[r][c + 3] = v.w;
        } else {
            rows[r][c + 0] = 0.f; rows[r][c + 1] = 0.f;
            rows[r][c + 2] = 0.f; rows[r][c + 3] = 0.f;
        }
    }
    __syncthreads();

    const int mtile = g16 >> 3, m16blk = g16 & 7;
    float4* outb = (float4*)g_xg;
    for (int u = tid; u < 1536; u += 256) {
        int kc = u >> 7, r = u & 127;
        int ks = r >> 5, t = r & 31;
        int gid = t >> 2, tig = t & 3;
        __half2 h[4];
#pragma unroll
        for (int j = 0; j < 4; j++) {
            int row = gid + 8 * (j & 1);
            int col = kc * 64 + ks * 16 + tig * 2 + 8 * (j >> 1);
            h[j] = __floats2half2_rn(rows[row][col], rows[row][col + 1]);
        }
        float4 v;
        v.x = __uint_as_float(*(uint32_t*)&h[0]);
        v.y = __uint_as_float(*(uint32_t*)&h[1]);
        v.z = __uint_as_float(*(uint32_t*)&h[2]);
        v.w = __uint_as_float(*(uint32_t*)&h[3]);
        outb[(((size_t)((e * MTILES + mtile) * KCH1 + kc)) << 10) + m16blk * 128 + ks * 32 + t] = v;
    }
}

// ---------------------------------------------------------------------------
// fp16 fragment-major GEMM. CTA 128x128, 4 warps (2x2), warp tile 64x64.
//   3-stage cp.async pipeline, prefetch interleaved into ks loop. (R11)
// ---------------------------------------------------------------------------
template<int NKCH, int NDIM, bool EPI_FRAG>
__global__ __launch_bounds__(128, 2) void gemm_f16_kernel(
    const __half* __restrict__ Ablobs,
    const __half* __restrict__ Bblobs,
    const float* __restrict__ bias,
    void* __restrict__ Cout)
{
    const int e  = blockIdx.z;
    const int Me = min(g_cnt[e], CAP);
    const int m0 = blockIdx.y * 128;
    if (m0 >= Me) return;
    const int bx = blockIdx.x;

    extern __shared__ float smem[];           // 3 stages x 8192 floats (32KB)
    const int tid = threadIdx.x;
    const int wid = tid >> 5, lid = tid & 31;
    const int gid = lid >> 2, tig = lid & 3;
    const int wMblk = (wid >> 1) * 4;
    const int pbase = (wid & 1) * 4;

    const float4* Ab = (const float4*)(Ablobs + (((size_t)(e * MTILES + blockIdx.y) * NKCH) << 13));
    const float4* Bb = (const float4*)(Bblobs + (((size_t)(e * (NDIM / 128) + bx) * NKCH) << 13));

    float acc[4][8][4];
#pragma unroll
    for (int mf = 0; mf < 4; mf++)
#pragma unroll
        for (int nf = 0; nf < 8; nf++)
#pragma unroll
            for (int q = 0; q < 4; q++) acc[mf][nf][q] = 0.f;

    auto issue_all = [&](int i) {
        float4* dst = (float4*)(smem + (i % 3) * 8192);
        const float4* a = Ab + ((size_t)i << 10);
        const float4* b = Bb + ((size_t)i << 10);
#pragma unroll
        for (int j = 0; j < 8; j++)
            cp16(dst + j * 128 + tid, a + j * 128 + tid);
#pragma unroll
        for (int j = 0; j < 8; j++)
            cp16(dst + 1024 + j * 128 + tid, b + j * 128 + tid);
        CP_COMMIT();
    };

    issue_all(0);
    issue_all(1);

    for (int i = 0; i < NKCH; i++) {
        CP_WAIT1();
        __syncthreads();

        const bool pf = (i + 2 < NKCH);
        float4* pdst = (float4*)(smem + ((i + 2) % 3) * 8192);
        const float4* pa = Ab + ((size_t)(i + 2) << 10);
        const float4* pb = Bb + ((size_t)(i + 2) << 10);

        const float4* pA = (const float4*)(smem + (i % 3) * 8192);
        const float4* pB = pA + 1024;
#pragma unroll
        for (int ks = 0; ks < 4; ks++) {
            uint32_t a[4][4], b[8][2];
#pragma unroll
            for (int mf = 0; mf < 4; mf++) {
                float4 v = pA[((wMblk + mf) * 4 + ks) * 32 + lid];
                a[mf][0] = __float_as_uint(v.x);
                a[mf][1] = __float_as_uint(v.y);
                a[mf][2] = __float_as_uint(v.z);
                a[mf][3] = __float_as_uint(v.w);
            }
#pragma unroll
            for (int q = 0; q < 4; q++) {
                float4 v = pB[(ks * 8 + pbase + q) * 32 + lid];
                b[2 * q + 0][0] = __float_as_uint(v.x);
                b[2 * q + 0][1] = __float_as_uint(v.y);
                b[2 * q + 1][0] = __float_as_uint(v.z);
                b[2 * q + 1][1] = __float_as_uint(v.w);
            }
            if (pf) {
#pragma unroll
                for (int j = ks * 4; j < ks * 4 + 4; j++) {
                    if (j < 8) cp16(pdst + j * 128 + tid, pa + j * 128 + tid);
                    else       cp16(pdst + 1024 + (j - 8) * 128 + tid,
                                    pb + (j - 8) * 128 + tid);
                }
            }
#pragma unroll
            for (int mf = 0; mf < 4; mf++)
#pragma unroll
                for (int nf = 0; nf < 8; nf++)
                    MMA_F16(acc[mf][nf], a[mf], b[nf]);
        }
        CP_COMMIT();
    }

    const int warpM = (wid >> 1) * 64;
    const int warpN = (wid & 1) * 64;
    const int n0 = bx * 128;
    const float* bp = bias + (size_t)e * NDIM + n0 + warpN;

    if (EPI_FRAG) {
        __syncthreads();
#pragma unroll
        for (int mf = 0; mf < 4; mf++)
#pragma unroll
            for (int half = 0; half < 2; half++) {
                int m_local = warpM + mf * 16 + gid + half * 8;
                int m16blk = m_local >> 4, mm = m_local & 15;
                int gid_a = mm & 7, ja_lo = mm >> 3;
#pragma unroll
                for (int nf = 0; nf < 8; nf++) {
                    int n_local = warpN + nf * 8 + tig * 2;
                    float v0 = acc[mf][nf][half * 2 + 0] + bp[nf * 8 + tig * 2 + 0];
                    float v1 = acc[mf][nf][half * 2 + 1] + bp[nf * 8 + tig * 2 + 1];
                    v0 = 0.5f * v0 * (1.f + erff(v0 * 0.70710678118654752f));
                    v1 = 0.5f * v1 * (1.f + erff(v1 * 0.70710678118654752f));
                    __half2 hv = __floats2half2_rn(v0, v1);
                    int kc_l = n_local >> 6;
                    int kin  = n_local & 63;
                    int ks = kin >> 4, kk = kin & 15;
                    int ja_hi = kk >> 3, tig_a = (kk & 7) >> 1;
                    int t_a = gid_a * 4 + tig_a;
                    int tw = t_a ^ (((t_a >> 3) & 3) << 1);
                    int q = kc_l * 1024 + (m16blk * 4 + ks) * 32 + tw;
                    ((__half2*)smem)[q * 4 + (ja_lo + 2 * ja_hi)] = hv;
                }
            }
        __syncthreads();
        float4* dst = (float4*)((__half*)Cout +
            (((size_t)((e * MTILES + blockIdx.y) * KCH2 + bx * 2)) << 13));
        const float4* st = (const float4*)smem;
#pragma unroll
        for (int u = tid; u < 2048; u += 128) {
            int t = u & 31;
            int tw = t ^ (((t >> 3) & 3) << 1);
            dst[u] = st[(u & ~31) | tw];
        }
    } else {
        float* Cf = (float*)Cout;
#pragma unroll
        for (int mf = 0; mf < 4; mf++)
#pragma unroll
            for (int half = 0; half < 2; half++) {
                int m = m0 + warpM + mf * 16 + gid + half * 8;
                if (m >= Me) continue;
                float* Crow = Cf + (size_t)(e * CAP + m) * NDIM + n0 + warpN;
#pragma unroll
                for (int nf = 0; nf < 8; nf++) {
                    float2 o;
                    o.x = acc[mf][nf][half * 2 + 0] + bp[nf * 8 + tig * 2 + 0];
                    o.y = acc[mf][nf][half * 2 + 1] + bp[nf * 8 + tig * 2 + 1];
                    *(float2*)(Crow + nf * 8 + tig * 2) = o;
                }
            }
    }
}

// ---------------------------------------------------------------------------
// combine + LayerNorm
// ---------------------------------------------------------------------------
__global__ __launch_bounds__(256) void combine_ln_kernel(
    const float* __restrict__ lnw,
    const float* __restrict__ lnb,
    float* __restrict__ out)
{
    const int t   = blockIdx.x;
    const int tid = threadIdx.x;
    const int s0  = g_slot[2 * t + 0];
    const int s1  = g_slot[2 * t + 1];
    const float w0 = g_route_w[2 * t + 0];
    const float w1 = g_route_w[2 * t + 1];

    float v[3];
    float sum = 0.f;
#pragma unroll
    for (int r = 0; r < 3; r++) {
        int i = r * 256 + tid;
        float a = (s0 >= 0) ? g_Y[(size_t)s0 * DIM + i] : 0.f;
        float b = (s1 >= 0) ? g_Y[(size_t)s1 * DIM + i] : 0.f;
        v[r] = w0 * a + w1 * b;
        sum += v[r];
    }

    __shared__ float red[256];
    red[tid] = sum;
    __syncthreads();
#pragma unroll
    for (int o = 128; o > 0; o >>= 1) {
        if (tid < o) red[tid] += red[tid + o];
        __syncthreads();
    }
    float mu = red[0] * (1.f / (float)DIM);
    __syncthreads();

    float sq = 0.f;
#pragma unroll
    for (int r = 0; r < 3; r++) { float d = v[r] - mu; sq += d * d; }
    red[tid] = sq;
    __syncthreads();
#pragma unroll
    for (int o = 128; o > 0; o >>= 1) {
        if (tid < o) red[tid] += red[tid + o];
        __syncthreads();
    }
    float rstd = rsqrtf(red[0] * (1.f / (float)DIM) + 1e-5f);

#pragma unroll
    for (int r = 0; r < 3; r++) {
        int i = r * 256 + tid;
        out[(size_t)t * DIM + i] = (v[r] - mu) * rstd * lnw[i] + lnb[i];
    }
}

// ---------------------------------------------------------------------------
// Launch:  prep(0), assign(1), gather(2), gemm1(3), gemm2(4), combine(5)
// ---------------------------------------------------------------------------
extern "C" void kernel_launch(void* const* d_in, const int* in_sizes, int n_in,
                              void* d_out, int out_size)
{
    const float* x   = (const float*)d_in[0];
    const float* wg  = (const float*)d_in[1];
    const float* w1  = (const float*)d_in[2];
    const float* b1  = (const float*)d_in[3];
    const float* w2  = (const float*)d_in[4];
    const float* b2  = (const float*)d_in[5];
    const float* lnw = (const float*)d_in[6];
    const float* lnb = (const float*)d_in[7];
    float* out = (float*)d_out;

    const int SMEM_BYTES = 3 * 8192 * 4;   // 98304
    cudaFuncSetAttribute(gemm_f16_kernel<KCH1, HID, true>,
                         cudaFuncAttributeMaxDynamicSharedMemorySize, SMEM_BYTES);
    cudaFuncSetAttribute(gemm_f16_kernel<KCH2, DIM, false>,
                         cudaFuncAttributeMaxDynamicSharedMemorySize, SMEM_BYTES);

    __half* w1f; cudaGetSymbolAddress((void**)&w1f, g_w1f);
    __half* w2f; cudaGetSymbolAddress((void**)&w2f, g_w2f);
    __half* xg;  cudaGetSymbolAddress((void**)&xg,  g_xg);
    __half* Hbuf; cudaGetSymbolAddress((void**)&Hbuf, g_H);
    float* Ybuf; cudaGetSymbolAddress((void**)&Ybuf, g_Y);

    prep_kernel<<<4096 + 4608, 256>>>(x, wg, w1, w2);
    assign_kernel<<<N_TOK / 256, 256>>>();
    gather_frag_kernel<<<dim3(CAP / 16, NEXP), 256>>>(x);

    gemm_f16_kernel<KCH1, HID, true><<<dim3(HID / 128, MTILES, NEXP), 128, SMEM_BYTES>>>(
        xg, w1f, b1, Hbuf);
    gemm_f16_kernel<KCH2, DIM, false><<<dim3(DIM / 128, MTILES, NEXP), 128, SMEM_BYTES>>>(
        Hbuf, w2f, b2, Ybuf);

    combine_ln_kernel<<<N_TOK, 256>>>(lnw, lnb, out);
}

// round 13
// speedup vs baseline: 2.5955x; 1.0790x over previous
#include <cuda_runtime.h>
#include <cuda_fp16.h>
#include <math.h>
#include <stdint.h>

#define N_TOK 32768
#define DIM   768
#define HID   3072
#define NEXP  8
#define CAP   10240
#define MTILES (CAP / 128)          // 80
#define KCH1  (DIM / 64)            // 12
#define KCH2  (HID / 64)            // 48

// ---------------------------------------------------------------------------
// Scratch. Fragment-major fp16 blobs, 16KB each (1024 float4 units).
// ---------------------------------------------------------------------------
__device__ int    g_cnt[NEXP];
__device__ int    g_route_e[N_TOK * 2];
__device__ float  g_route_w[N_TOK * 2];
__device__ int    g_tokidx[NEXP * CAP];
__device__ int    g_slot[N_TOK * 2];
__device__ __half g_xg [(size_t)NEXP * CAP * DIM];
__device__ __half g_w1f[(size_t)NEXP * DIM * HID];
__device__ __half g_w2f[(size_t)NEXP * HID * DIM];
__device__ __half g_H  [(size_t)NEXP * CAP * HID];
__device__ float  g_Y  [(size_t)NEXP * CAP * DIM];

// ---------------------------------------------------------------------------
// Helpers
// ---------------------------------------------------------------------------
__device__ __forceinline__ void cp16s(uint32_t dst, const void* src) {
    asm volatile("cp.async.cg.shared.global [%0], [%1], 16;" :: "r"(dst), "l"(src));
}
#define CP_COMMIT() asm volatile("cp.async.commit_group;" ::: "memory")
#define CP_WAIT1()  asm volatile("cp.async.wait_group 1;" ::: "memory")

#define MMA_F16(c, a, b) \
    asm volatile("mma.sync.aligned.m16n8k16.row.col.f32.f16.f16.f32 " \
        "{%0,%1,%2,%3}, {%4,%5,%6,%7}, {%8,%9}, {%0,%1,%2,%3};" \
        : "+f"((c)[0]), "+f"((c)[1]), "+f"((c)[2]), "+f"((c)[3]) \
        : "r"((a)[0]), "r"((a)[1]), "r"((a)[2]), "r"((a)[3]), \
          "r"((b)[0]), "r"((b)[1]))

// ---------------------------------------------------------------------------
// Kernel 0: PREP = zero counters + router + both weight->blob transforms.
// ---------------------------------------------------------------------------
__global__ __launch_bounds__(256) void prep_kernel(
    const float* __restrict__ x,  const float* __restrict__ wg,
    const float* __restrict__ w1, const float* __restrict__ w2)
{
    __shared__ float tile[64][132];
    const int b = blockIdx.x;
    const int tid = threadIdx.x;

    if (b < 4096) {
        if (b == 0 && tid < NEXP) g_cnt[tid] = 0;
        int warp = b * 8 + (tid >> 5);
        int lane = tid & 31;
        const float* xr = x + (size_t)warp * DIM;

        float acc[NEXP];
#pragma unroll
        for (int e = 0; e < NEXP; e++) acc[e] = 0.f;
        for (int j = lane; j < DIM; j += 32) {
            float xv = xr[j];
            const float* wr = wg + j * NEXP;
#pragma unroll
            for (int e = 0; e < NEXP; e++) acc[e] += xv * wr[e];
        }
#pragma unroll
        for (int e = 0; e < NEXP; e++) {
#pragma unroll
            for (int o = 16; o > 0; o >>= 1)
                acc[e] += __shfl_xor_sync(0xffffffffu, acc[e], o);
        }
        if (lane == 0) {
            int e0 = 0; float v0 = acc[0];
#pragma unroll
            for (int e = 1; e < NEXP; e++) if (acc[e] > v0) { v0 = acc[e]; e0 = e; }
            int e1 = -1; float v1 = -3.4e38f;
#pragma unroll
            for (int e = 0; e < NEXP; e++) if (e != e0 && acc[e] > v1) { v1 = acc[e]; e1 = e; }
            float ex = expf(v1 - v0);
            float s  = 1.f + ex;
            g_route_e[2 * warp + 0] = e0;  g_route_w[2 * warp + 0] = 1.f / s;
            g_route_e[2 * warp + 1] = e1;  g_route_w[2 * warp + 1] = ex / s;
        }
        return;
    }

    int wb = b - 4096;
    const float* w;
    __half* out;
    int KD, nkc;
    size_t ndiv;
    if (wb < 2304) { w = w1; out = g_w1f; KD = DIM; nkc = 12; ndiv = HID / 128; }
    else           { wb -= 2304; w = w2; out = g_w2f; KD = HID; nkc = 48; ndiv = DIM / 128; }
    const int ND = (int)(ndiv * 128);
    const int e  = wb / 288;
    const int r  = wb % 288;
    const int nt = r / nkc;
    const int kc = r % nkc;

    const float* src = w + ((size_t)e * KD + kc * 64) * ND + nt * 128;
#pragma unroll
    for (int u = tid; u < 2048; u += 256) {
        int rr = u >> 5, c = (u & 31) * 4;
        float4 v = *(const float4*)(src + (size_t)rr * ND + c);
        tile[rr][c + 0] = v.x; tile[rr][c + 1] = v.y;
        tile[rr][c + 2] = v.z; tile[rr][c + 3] = v.w;
    }
    __syncthreads();

    float4* dst = (float4*)(out + (((size_t)(e * ndiv + nt) * nkc + kc) << 13));
#pragma unroll
    for (int u = tid; u < 1024; u += 256) {
        int t = u & 31, pp = (u >> 5) & 7, ks = u >> 8;
        int gid = t >> 2, tig = t & 3;
        __half2 h[4];
#pragma unroll
        for (int j = 0; j < 4; j++) {
            int n = pp * 16 + 8 * (j >> 1) + gid;
            int k = ks * 16 + tig * 2 + 8 * (j & 1);
            h[j] = __floats2half2_rn(tile[k][n], tile[k + 1][n]);
        }
        float4 v;
        v.x = __uint_as_float(*(uint32_t*)&h[0]);
        v.y = __uint_as_float(*(uint32_t*)&h[1]);
        v.z = __uint_as_float(*(uint32_t*)&h[2]);
        v.w = __uint_as_float(*(uint32_t*)&h[3]);
        dst[u] = v;
    }
}

// ---------------------------------------------------------------------------
// Kernel 1: slot assignment
// ---------------------------------------------------------------------------
__global__ void assign_kernel() {
    int t = blockIdx.x * blockDim.x + threadIdx.x;
    if (t >= N_TOK) return;
#pragma unroll
    for (int k = 0; k < 2; k++) {
        int e = g_route_e[2 * t + k];
        int pos = atomicAdd(&g_cnt[e], 1);
        if (pos < CAP) {
            g_tokidx[e * CAP + pos] = t;
            g_slot[2 * t + k] = e * CAP + pos;
        } else {
            g_slot[2 * t + k] = -1;
        }
    }
}

// ---------------------------------------------------------------------------
// Kernel 2: gather routed tokens into fp16 A-blobs
// ---------------------------------------------------------------------------
__global__ __launch_bounds__(256) void gather_frag_kernel(const float* __restrict__ x) {
    const int e = blockIdx.y;
    const int Me = min(g_cnt[e], CAP);
    const int g16 = blockIdx.x;
    const int base = g16 * 16;
    if (base >= Me) return;

    __shared__ float rows[16][772];
    const int tid = threadIdx.x;

    for (int u = tid; u < 16 * 192; u += 256) {
        int r = u / 192, c = (u % 192) * 4;
        int pos = base + r;
        if (pos < Me) {
            int tok = g_tokidx[e * CAP + pos];
            float4 v = *(const float4*)(x + (size_t)tok * DIM + c);
            rows[r][c + 0] = v.x; rows[r][c + 1] = v.y;
            rows[r][c + 2] = v.z; rows[r][c + 3] = v.w;
        } else {
            rows[r][c + 0] = 0.f; rows[r][c + 1] = 0.f;
            rows[r][c + 2] = 0.f; rows[r][c + 3] = 0.f;
        }
    }
    __syncthreads();

    const int mtile = g16 >> 3, m16blk = g16 & 7;
    float4* outb = (float4*)g_xg;
    for (int u = tid; u < 1536; u += 256) {
        int kc = u >> 7, r = u & 127;
        int ks = r >> 5, t = r & 31;
        int gid = t >> 2, tig = t & 3;
        __half2 h[4];
#pragma unroll
        for (int j = 0; j < 4; j++) {
            int row = gid + 8 * (j & 1);
            int col = kc * 64 + ks * 16 + tig * 2 + 8 * (j >> 1);
            h[j] = __floats2half2_rn(rows[row][col], rows[row][col + 1]);
        }
        float4 v;
        v.x = __uint_as_float(*(uint32_t*)&h[0]);
        v.y = __uint_as_float(*(uint32_t*)&h[1]);
        v.z = __uint_as_float(*(uint32_t*)&h[2]);
        v.w = __uint_as_float(*(uint32_t*)&h[3]);
        outb[(((size_t)((e * MTILES + mtile) * KCH1 + kc)) << 10) + m16blk * 128 + ks * 32 + t] = v;
    }
}

// ---------------------------------------------------------------------------
// fp16 fragment-major GEMM. CTA 128x128, 4 warps (2x2), warp tile 64x64.
//   Strength-reduced mainloop: 3x-unrolled stage ring (compile-time stage
//   offsets), running global src pointers, one cvta. All inner addresses are
//   base-reg + immediate.
// ---------------------------------------------------------------------------
template<int NKCH, int NDIM, bool EPI_FRAG>
__global__ __launch_bounds__(128, 2) void gemm_f16_kernel(
    const __half* __restrict__ Ablobs,
    const __half* __restrict__ Bblobs,
    const float* __restrict__ bias,
    void* __restrict__ Cout)
{
    static_assert(NKCH % 3 == 0, "stage ring requires NKCH % 3 == 0");
    const int e  = blockIdx.z;
    const int Me = min(g_cnt[e], CAP);
    const int m0 = blockIdx.y * 128;
    if (m0 >= Me) return;
    const int bx = blockIdx.x;

    extern __shared__ float smem[];           // 3 stages x 8192 floats (32KB)
    const int tid = threadIdx.x;
    const int wid = tid >> 5, lid = tid & 31;
    const int gid = lid >> 2, tig = lid & 3;
    const int wMblk = (wid >> 1) * 4;
    const int pbase = (wid & 1) * 4;

    const float4* Ab = (const float4*)(Ablobs + (((size_t)(e * MTILES + blockIdx.y) * NKCH) << 13));
    const float4* Bb = (const float4*)(Bblobs + (((size_t)(e * (NDIM / 128) + bx) * NKCH) << 13));

    // one cvta; all cp.async dsts are cpd + stage/chunk immediates
    uint32_t cpd;
    asm("{ .reg .u64 t; cvta.to.shared.u64 t, %1; cvt.u32.u64 %0, t; }"
        : "=r"(cpd) : "l"(smem));
    cpd += tid * 16;

    // loop-invariant fragment base pointers (stage offset added as immediate)
    const float4* fA = (const float4*)smem + wMblk * 128 + lid;   // (wMblk*4)*32
    const float4* fB = (const float4*)smem + 1024 + pbase * 32 + lid;

    float acc[4][8][4];
#pragma unroll
    for (int mf = 0; mf < 4; mf++)
#pragma unroll
        for (int nf = 0; nf < 8; nf++)
#pragma unroll
            for (int q = 0; q < 4; q++) acc[mf][nf][q] = 0.f;

    // prologue: full issue of chunks 0 and 1
    {
        const float4* a0 = Ab + tid;
        const float4* b0 = Bb + tid;
#pragma unroll
        for (int s = 0; s < 2; s++) {
#pragma unroll
            for (int j = 0; j < 8; j++)
                cp16s(cpd + s * 32768 + j * 2048, a0 + s * 1024 + j * 128);
#pragma unroll
            for (int j = 0; j < 8; j++)
                cp16s(cpd + s * 32768 + 16384 + j * 2048, b0 + s * 1024 + j * 128);
            CP_COMMIT();
        }
    }

    // running prefetch sources (chunk i+2 when processing chunk i)
    const float4* gpa = Ab + 2048 + tid;
    const float4* gpb = Bb + 2048 + tid;

    // body macro: S_CUR/S_PF are literal stage indices (0/1/2)
#define GEMM_BODY(ICHUNK, S_CUR, S_PF)                                         \
    {                                                                          \
        const bool pf = ((ICHUNK) + 2 < NKCH);                                 \
        CP_WAIT1();                                                            \
        __syncthreads();                                                       \
        _Pragma("unroll")                                                      \
        for (int ks = 0; ks < 4; ks++) {                                       \
            uint32_t a[4][4], b[8][2];                                         \
            _Pragma("unroll")                                                  \
            for (int mf = 0; mf < 4; mf++) {                                   \
                float4 v = fA[(S_CUR) * 2048 + mf * 128 + ks * 32];            \
                a[mf][0] = __float_as_uint(v.x);                               \
                a[mf][1] = __float_as_uint(v.y);                               \
                a[mf][2] = __float_as_uint(v.z);                               \
                a[mf][3] = __float_as_uint(v.w);                               \
            }                                                                  \
            _Pragma("unroll")                                                  \
            for (int q = 0; q < 4; q++) {                                      \
                float4 v = fB[(S_CUR) * 2048 + ks * 256 + q * 32];             \
                b[2 * q + 0][0] = __float_as_uint(v.x);                        \
                b[2 * q + 0][1] = __float_as_uint(v.y);                        \
                b[2 * q + 1][0] = __float_as_uint(v.z);                        \
                b[2 * q + 1][1] = __float_as_uint(v.w);                        \
            }                                                                  \
            if (pf) {                                                          \
                _Pragma("unroll")                                              \
                for (int jj = 0; jj < 4; jj++) {                               \
                    int j = ks * 4 + jj;                                       \
                    if (j < 8) cp16s(cpd + (S_PF) * 32768 + j * 2048,          \
                                     gpa + j * 128);                           \
                    else       cp16s(cpd + (S_PF) * 32768 + 16384 + (j - 8) * 2048, \
                                     gpb + (j - 8) * 128);                     \
                }                                                              \
            }                                                                  \
            _Pragma("unroll")                                                  \
            for (int mf = 0; mf < 4; mf++)                                     \
                _Pragma("unroll")                                              \
                for (int nf = 0; nf < 8; nf++)                                 \
                    MMA_F16(acc[mf][nf], a[mf], b[nf]);                        \
        }                                                                      \
        CP_COMMIT();                                                           \
        gpa += 1024; gpb += 1024;                                              \
    }

    for (int i = 0; i < NKCH; i += 3) {
        GEMM_BODY(i,     0, 2)
        GEMM_BODY(i + 1, 1, 0)
        GEMM_BODY(i + 2, 2, 1)
    }
#undef GEMM_BODY

    const int warpM = (wid >> 1) * 64;
    const int warpN = (wid & 1) * 64;
    const int n0 = bx * 128;
    const float* bp = bias + (size_t)e * NDIM + n0 + warpN;

    if (EPI_FRAG) {
        __syncthreads();
#pragma unroll
        for (int mf = 0; mf < 4; mf++)
#pragma unroll
            for (int half = 0; half < 2; half++) {
                int m_local = warpM + mf * 16 + gid + half * 8;
                int m16blk = m_local >> 4, mm = m_local & 15;
                int gid_a = mm & 7, ja_lo = mm >> 3;
#pragma unroll
                for (int nf = 0; nf < 8; nf++) {
                    int n_local = warpN + nf * 8 + tig * 2;
                    float v0 = acc[mf][nf][half * 2 + 0] + bp[nf * 8 + tig * 2 + 0];
                    float v1 = acc[mf][nf][half * 2 + 1] + bp[nf * 8 + tig * 2 + 1];
                    v0 = 0.5f * v0 * (1.f + erff(v0 * 0.70710678118654752f));
                    v1 = 0.5f * v1 * (1.f + erff(v1 * 0.70710678118654752f));
                    __half2 hv = __floats2half2_rn(v0, v1);
                    int kc_l = n_local >> 6;
                    int kin  = n_local & 63;
                    int ks = kin >> 4, kk = kin & 15;
                    int ja_hi = kk >> 3, tig_a = (kk & 7) >> 1;
                    int t_a = gid_a * 4 + tig_a;
                    int tw = t_a ^ (((t_a >> 3) & 3) << 1);
                    int q = kc_l * 1024 + (m16blk * 4 + ks) * 32 + tw;
                    ((__half2*)smem)[q * 4 + (ja_lo + 2 * ja_hi)] = hv;
                }
            }
        __syncthreads();
        float4* dst = (float4*)((__half*)Cout +
            (((size_t)((e * MTILES + blockIdx.y) * KCH2 + bx * 2)) << 13));
        const float4* st = (const float4*)smem;
#pragma unroll
        for (int u = tid; u < 2048; u += 128) {
            int t = u & 31;
            int tw = t ^ (((t >> 3) & 3) << 1);
            dst[u] = st[(u & ~31) | tw];
        }
    } else {
        float* Cf = (float*)Cout;
#pragma unroll
        for (int mf = 0; mf < 4; mf++)
#pragma unroll
            for (int half = 0; half < 2; half++) {
                int m = m0 + warpM + mf * 16 + gid + half * 8;
                if (m >= Me) continue;
                float* Crow = Cf + (size_t)(e * CAP + m) * NDIM + n0 + warpN;
#pragma unroll
                for (int nf = 0; nf < 8; nf++) {
                    float2 o;
                    o.x = acc[mf][nf][half * 2 + 0] + bp[nf * 8 + tig * 2 + 0];
                    o.y = acc[mf][nf][half * 2 + 1] + bp[nf * 8 + tig * 2 + 1];
                    *(float2*)(Crow + nf * 8 + tig * 2) = o;
                }
            }
    }
}

// ---------------------------------------------------------------------------
// combine + LayerNorm
// ---------------------------------------------------------------------------
__global__ __launch_bounds__(256) void combine_ln_kernel(
    const float* __restrict__ lnw,
    const float* __restrict__ lnb,
    float* __restrict__ out)
{
    const int t   = blockIdx.x;
    const int tid = threadIdx.x;
    const int s0  = g_slot[2 * t + 0];
    const int s1  = g_slot[2 * t + 1];
    const float w0 = g_route_w[2 * t + 0];
    const float w1 = g_route_w[2 * t + 1];

    float v[3];
    float sum = 0.f;
#pragma unroll
    for (int r = 0; r < 3; r++) {
        int i = r * 256 + tid;
        float a = (s0 >= 0) ? g_Y[(size_t)s0 * DIM + i] : 0.f;
        float b = (s1 >= 0) ? g_Y[(size_t)s1 * DIM + i] : 0.f;
        v[r] = w0 * a + w1 * b;
        sum += v[r];
    }

    __shared__ float red[256];
    red[tid] = sum;
    __syncthreads();
#pragma unroll
    for (int o = 128; o > 0; o >>= 1) {
        if (tid < o) red[tid] += red[tid + o];
        __syncthreads();
    }
    float mu = red[0] * (1.f / (float)DIM);
    __syncthreads();

    float sq = 0.f;
#pragma unroll
    for (int r = 0; r < 3; r++) { float d = v[r] - mu; sq += d * d; }
    red[tid] = sq;
    __syncthreads();
#pragma unroll
    for (int o = 128; o > 0; o >>= 1) {
        if (tid < o) red[tid] += red[tid + o];
        __syncthreads();
    }
    float rstd = rsqrtf(red[0] * (1.f / (float)DIM) + 1e-5f);

#pragma unroll
    for (int r = 0; r < 3; r++) {
        int i = r * 256 + tid;
        out[(size_t)t * DIM + i] = (v[r] - mu) * rstd * lnw[i] + lnb[i];
    }
}

// ---------------------------------------------------------------------------
// Launch:  prep(0), assign(1), gather(2), gemm1(3), gemm2(4), combine(5)
// ---------------------------------------------------------------------------
extern "C" void kernel_launch(void* const* d_in, const int* in_sizes, int n_in,
                              void* d_out, int out_size)
{
    const float* x   = (const float*)d_in[0];
    const float* wg  = (const float*)d_in[1];
    const float* w1  = (const float*)d_in[2];
    const float* b1  = (const float*)d_in[3];
    const float* w2  = (const float*)d_in[4];
    const float* b2  = (const float*)d_in[5];
    const float* lnw = (const float*)d_in[6];
    const float* lnb = (const float*)d_in[7];
    float* out = (float*)d_out;

    const int SMEM_BYTES = 3 * 8192 * 4;   // 98304
    cudaFuncSetAttribute(gemm_f16_kernel<KCH1, HID, true>,
                         cudaFuncAttributeMaxDynamicSharedMemorySize, SMEM_BYTES);
    cudaFuncSetAttribute(gemm_f16_kernel<KCH2, DIM, false>,
                         cudaFuncAttributeMaxDynamicSharedMemorySize, SMEM_BYTES);

    __half* w1f; cudaGetSymbolAddress((void**)&w1f, g_w1f);
    __half* w2f; cudaGetSymbolAddress((void**)&w2f, g_w2f);
    __half* xg;  cudaGetSymbolAddress((void**)&xg,  g_xg);
    __half* Hbuf; cudaGetSymbolAddress((void**)&Hbuf, g_H);
    float* Ybuf; cudaGetSymbolAddress((void**)&Ybuf, g_Y);

    prep_kernel<<<4096 + 4608, 256>>>(x, wg, w1, w2);
    assign_kernel<<<N_TOK / 256, 256>>>();
    gather_frag_kernel<<<dim3(CAP / 16, NEXP), 256>>>(x);

    gemm_f16_kernel<KCH1, HID, true><<<dim3(HID / 128, MTILES, NEXP), 128, SMEM_BYTES>>>(
        xg, w1f, b1, Hbuf);
    gemm_f16_kernel<KCH2, DIM, false><<<dim3(DIM / 128, MTILES, NEXP), 128, SMEM_BYTES>>>(
        Hbuf, w2f, b2, Ybuf);

    combine_ln_kernel<<<N_TOK, 256>>>(lnw, lnb, out);
}

// round 14
// speedup vs baseline: 2.6272x; 1.0122x over previous
#include <cuda_runtime.h>
#include <cuda_fp16.h>
#include <math.h>
#include <stdint.h>

#define N_TOK 32768
#define DIM   768
#define HID   3072
#define NEXP  8
#define CAP   10240
#define MTILES (CAP / 128)          // 80
#define KCH1  (DIM / 64)            // 12
#define KCH2  (HID / 64)            // 48

// ---------------------------------------------------------------------------
// Scratch. Fragment-major fp16 blobs, 16KB each (1024 float4 units).
// ---------------------------------------------------------------------------
__device__ int    g_cnt[NEXP];
__device__ int    g_route_e[N_TOK * 2];
__device__ float  g_route_w[N_TOK * 2];
__device__ int    g_tokidx[NEXP * CAP];
__device__ int    g_slot[N_TOK * 2];
__device__ __half g_xg [(size_t)NEXP * CAP * DIM];
__device__ __half g_w1f[(size_t)NEXP * DIM * HID];
__device__ __half g_w2f[(size_t)NEXP * HID * DIM];
__device__ __half g_H  [(size_t)NEXP * CAP * HID];
__device__ float  g_Y  [(size_t)NEXP * CAP * DIM];

// ---------------------------------------------------------------------------
// Helpers
// ---------------------------------------------------------------------------
__device__ __forceinline__ void cp16s(uint32_t dst, const void* src) {
    asm volatile("cp.async.cg.shared.global [%0], [%1], 16;" :: "r"(dst), "l"(src));
}
#define CP_COMMIT() asm volatile("cp.async.commit_group;" ::: "memory")
#define CP_WAIT1()  asm volatile("cp.async.wait_group 1;" ::: "memory")

#define MMA_F16(c, a, b) \
    asm volatile("mma.sync.aligned.m16n8k16.row.col.f32.f16.f16.f32 " \
        "{%0,%1,%2,%3}, {%4,%5,%6,%7}, {%8,%9}, {%0,%1,%2,%3};" \
        : "+f"((c)[0]), "+f"((c)[1]), "+f"((c)[2]), "+f"((c)[3]) \
        : "r"((a)[0]), "r"((a)[1]), "r"((a)[2]), "r"((a)[3]), \
          "r"((b)[0]), "r"((b)[1]))

__device__ __forceinline__ float gelu_exact(float v) {
    return 0.5f * v * (1.f + erff(v * 0.70710678118654752f));
}

// ---------------------------------------------------------------------------
// Kernel 0: PREP = zero counters + router + both weight->blob transforms.
// ---------------------------------------------------------------------------
__global__ __launch_bounds__(256) void prep_kernel(
    const float* __restrict__ x,  const float* __restrict__ wg,
    const float* __restrict__ w1, const float* __restrict__ w2)
{
    __shared__ float tile[64][132];
    const int b = blockIdx.x;
    const int tid = threadIdx.x;

    if (b < 4096) {
        if (b == 0 && tid < NEXP) g_cnt[tid] = 0;
        int warp = b * 8 + (tid >> 5);
        int lane = tid & 31;
        const float* xr = x + (size_t)warp * DIM;

        float acc[NEXP];
#pragma unroll
        for (int e = 0; e < NEXP; e++) acc[e] = 0.f;
        for (int j = lane; j < DIM; j += 32) {
            float xv = xr[j];
            const float* wr = wg + j * NEXP;
#pragma unroll
            for (int e = 0; e < NEXP; e++) acc[e] += xv * wr[e];
        }
#pragma unroll
        for (int e = 0; e < NEXP; e++) {
#pragma unroll
            for (int o = 16; o > 0; o >>= 1)
                acc[e] += __shfl_xor_sync(0xffffffffu, acc[e], o);
        }
        if (lane == 0) {
            int e0 = 0; float v0 = acc[0];
#pragma unroll
            for (int e = 1; e < NEXP; e++) if (acc[e] > v0) { v0 = acc[e]; e0 = e; }
            int e1 = -1; float v1 = -3.4e38f;
#pragma unroll
            for (int e = 0; e < NEXP; e++) if (e != e0 && acc[e] > v1) { v1 = acc[e]; e1 = e; }
            float ex = expf(v1 - v0);
            float s  = 1.f + ex;
            g_route_e[2 * warp + 0] = e0;  g_route_w[2 * warp + 0] = 1.f / s;
            g_route_e[2 * warp + 1] = e1;  g_route_w[2 * warp + 1] = ex / s;
        }
        return;
    }

    int wb = b - 4096;
    const float* w;
    __half* out;
    int KD, nkc;
    size_t ndiv;
    if (wb < 2304) { w = w1; out = g_w1f; KD = DIM; nkc = 12; ndiv = HID / 128; }
    else           { wb -= 2304; w = w2; out = g_w2f; KD = HID; nkc = 48; ndiv = DIM / 128; }
    const int ND = (int)(ndiv * 128);
    const int e  = wb / 288;
    const int r  = wb % 288;
    const int nt = r / nkc;
    const int kc = r % nkc;

    const float* src = w + ((size_t)e * KD + kc * 64) * ND + nt * 128;
#pragma unroll
    for (int u = tid; u < 2048; u += 256) {
        int rr = u >> 5, c = (u & 31) * 4;
        float4 v = *(const float4*)(src + (size_t)rr * ND + c);
        tile[rr][c + 0] = v.x; tile[rr][c + 1] = v.y;
        tile[rr][c + 2] = v.z; tile[rr][c + 3] = v.w;
    }
    __syncthreads();

    float4* dst = (float4*)(out + (((size_t)(e * ndiv + nt) * nkc + kc) << 13));
#pragma unroll
    for (int u = tid; u < 1024; u += 256) {
        int t = u & 31, pp = (u >> 5) & 7, ks = u >> 8;
        int gid = t >> 2, tig = t & 3;
        __half2 h[4];
#pragma unroll
        for (int j = 0; j < 4; j++) {
            int n = pp * 16 + 8 * (j >> 1) + gid;
            int k = ks * 16 + tig * 2 + 8 * (j & 1);
            h[j] = __floats2half2_rn(tile[k][n], tile[k + 1][n]);
        }
        float4 v;
        v.x = __uint_as_float(*(uint32_t*)&h[0]);
        v.y = __uint_as_float(*(uint32_t*)&h[1]);
        v.z = __uint_as_float(*(uint32_t*)&h[2]);
        v.w = __uint_as_float(*(uint32_t*)&h[3]);
        dst[u] = v;
    }
}

// ---------------------------------------------------------------------------
// Kernel 1: slot assignment
// ---------------------------------------------------------------------------
__global__ void assign_kernel() {
    int t = blockIdx.x * blockDim.x + threadIdx.x;
    if (t >= N_TOK) return;
#pragma unroll
    for (int k = 0; k < 2; k++) {
        int e = g_route_e[2 * t + k];
        int pos = atomicAdd(&g_cnt[e], 1);
        if (pos < CAP) {
            g_tokidx[e * CAP + pos] = t;
            g_slot[2 * t + k] = e * CAP + pos;
        } else {
            g_slot[2 * t + k] = -1;
        }
    }
}

// ---------------------------------------------------------------------------
// Kernel 2: gather routed tokens into fp16 A-blobs
// ---------------------------------------------------------------------------
__global__ __launch_bounds__(256) void gather_frag_kernel(const float* __restrict__ x) {
    const int e = blockIdx.y;
    const int Me = min(g_cnt[e], CAP);
    const int g16 = blockIdx.x;
    const int base = g16 * 16;
    if (base >= Me) return;

    __shared__ float rows[16][772];
    const int tid = threadIdx.x;

    for (int u = tid; u < 16 * 192; u += 256) {
        int r = u / 192, c = (u % 192) * 4;
        int pos = base + r;
        if (pos < Me) {
            int tok = g_tokidx[e * CAP + pos];
            float4 v = *(const float4*)(x + (size_t)tok * DIM + c);
            rows[r][c + 0] = v.x; rows[r][c + 1] = v.y;
            rows[r][c + 2] = v.z; rows[r][c + 3] = v.w;
        } else {
            rows[r][c + 0] = 0.f; rows[r][c + 1] = 0.f;
            rows[r][c + 2] = 0.f; rows[r][c + 3] = 0.f;
        }
    }
    __syncthreads();

    const int mtile = g16 >> 3, m16blk = g16 & 7;
    float4* outb = (float4*)g_xg;
    for (int u = tid; u < 1536; u += 256) {
        int kc = u >> 7, r = u & 127;
        int ks = r >> 5, t = r & 31;
        int gid = t >> 2, tig = t & 3;
        __half2 h[4];
#pragma unroll
        for (int j = 0; j < 4; j++) {
            int row = gid + 8 * (j & 1);
            int col = kc * 64 + ks * 16 + tig * 2 + 8 * (j >> 1);
            h[j] = __floats2half2_rn(rows[row][col], rows[row][col + 1]);
        }
        float4 v;
        v.x = __uint_as_float(*(uint32_t*)&h[0]);
        v.y = __uint_as_float(*(uint32_t*)&h[1]);
        v.z = __uint_as_float(*(uint32_t*)&h[2]);
        v.w = __uint_as_float(*(uint32_t*)&h[3]);
        outb[(((size_t)((e * MTILES + mtile) * KCH1 + kc)) << 10) + m16blk * 128 + ks * 32 + t] = v;
    }
}

// ---------------------------------------------------------------------------
// fp16 fragment-major GEMM. CTA 128x128, 4 warps (2x2), warp tile 64x64.
//   Strength-reduced mainloop (R13) + strength-reduced epilogue (R14):
//   gemm1 epilogue addresses pre-folded to base+immediate, STS.64, bias
//   preloaded to registers.
// ---------------------------------------------------------------------------
template<int NKCH, int NDIM, bool EPI_FRAG>
__global__ __launch_bounds__(128, 2) void gemm_f16_kernel(
    const __half* __restrict__ Ablobs,
    const __half* __restrict__ Bblobs,
    const float* __restrict__ bias,
    void* __restrict__ Cout)
{
    static_assert(NKCH % 3 == 0, "stage ring requires NKCH % 3 == 0");
    const int e  = blockIdx.z;
    const int Me = min(g_cnt[e], CAP);
    const int m0 = blockIdx.y * 128;
    if (m0 >= Me) return;
    const int bx = blockIdx.x;

    extern __shared__ float smem[];           // 3 stages x 8192 floats (32KB)
    const int tid = threadIdx.x;
    const int wid = tid >> 5, lid = tid & 31;
    const int gid = lid >> 2, tig = lid & 3;
    const int wMblk = (wid >> 1) * 4;
    const int pbase = (wid & 1) * 4;

    const float4* Ab = (const float4*)(Ablobs + (((size_t)(e * MTILES + blockIdx.y) * NKCH) << 13));
    const float4* Bb = (const float4*)(Bblobs + (((size_t)(e * (NDIM / 128) + bx) * NKCH) << 13));

    uint32_t cpd;
    asm("{ .reg .u64 t; cvta.to.shared.u64 t, %1; cvt.u32.u64 %0, t; }"
        : "=r"(cpd) : "l"(smem));
    cpd += tid * 16;

    const float4* fA = (const float4*)smem + wMblk * 128 + lid;
    const float4* fB = (const float4*)smem + 1024 + pbase * 32 + lid;

    float acc[4][8][4];
#pragma unroll
    for (int mf = 0; mf < 4; mf++)
#pragma unroll
        for (int nf = 0; nf < 8; nf++)
#pragma unroll
            for (int q = 0; q < 4; q++) acc[mf][nf][q] = 0.f;

    // prologue: full issue of chunks 0 and 1
    {
        const float4* a0 = Ab + tid;
        const float4* b0 = Bb + tid;
#pragma unroll
        for (int s = 0; s < 2; s++) {
#pragma unroll
            for (int j = 0; j < 8; j++)
                cp16s(cpd + s * 32768 + j * 2048, a0 + s * 1024 + j * 128);
#pragma unroll
            for (int j = 0; j < 8; j++)
                cp16s(cpd + s * 32768 + 16384 + j * 2048, b0 + s * 1024 + j * 128);
            CP_COMMIT();
        }
    }

    const float4* gpa = Ab + 2048 + tid;
    const float4* gpb = Bb + 2048 + tid;

#define GEMM_BODY(ICHUNK, S_CUR, S_PF)                                         \
    {                                                                          \
        const bool pf = ((ICHUNK) + 2 < NKCH);                                 \
        CP_WAIT1();                                                            \
        __syncthreads();                                                       \
        _Pragma("unroll")                                                      \
        for (int ks = 0; ks < 4; ks++) {                                       \
            uint32_t a[4][4], b[8][2];                                         \
            _Pragma("unroll")                                                  \
            for (int mf = 0; mf < 4; mf++) {                                   \
                float4 v = fA[(S_CUR) * 2048 + mf * 128 + ks * 32];            \
                a[mf][0] = __float_as_uint(v.x);                               \
                a[mf][1] = __float_as_uint(v.y);                               \
                a[mf][2] = __float_as_uint(v.z);                               \
                a[mf][3] = __float_as_uint(v.w);                               \
            }                                                                  \
            _Pragma("unroll")                                                  \
            for (int q = 0; q < 4; q++) {                                      \
                float4 v = fB[(S_CUR) * 2048 + ks * 256 + q * 32];             \
                b[2 * q + 0][0] = __float_as_uint(v.x);                        \
                b[2 * q + 0][1] = __float_as_uint(v.y);                        \
                b[2 * q + 1][0] = __float_as_uint(v.z);                        \
                b[2 * q + 1][1] = __float_as_uint(v.w);                        \
            }                                                                  \
            if (pf) {                                                          \
                _Pragma("unroll")                                              \
                for (int jj = 0; jj < 4; jj++) {                               \
                    int j = ks * 4 + jj;                                       \
                    if (j < 8) cp16s(cpd + (S_PF) * 32768 + j * 2048,          \
                                     gpa + j * 128);                           \
                    else       cp16s(cpd + (S_PF) * 32768 + 16384 + (j - 8) * 2048, \
                                     gpb + (j - 8) * 128);                     \
                }                                                              \
            }                                                                  \
            _Pragma("unroll")                                                  \
            for (int mf = 0; mf < 4; mf++)                                     \
                _Pragma("unroll")                                              \
                for (int nf = 0; nf < 8; nf++)                                 \
                    MMA_F16(acc[mf][nf], a[mf], b[nf]);                        \
        }                                                                      \
        CP_COMMIT();                                                           \
        gpa += 1024; gpb += 1024;                                              \
    }

    for (int i = 0; i < NKCH; i += 3) {
        GEMM_BODY(i,     0, 2)
        GEMM_BODY(i + 1, 1, 0)
        GEMM_BODY(i + 2, 2, 1)
    }
#undef GEMM_BODY

    const int warpM = (wid >> 1) * 64;
    const int warpN = (wid & 1) * 64;
    const int n0 = bx * 128;
    const float* bp = bias + (size_t)e * NDIM + n0 + warpN;

    // bias preload: value at column (warpN + nf*8 + tig*2 + c)
    float2 br[8];
#pragma unroll
    for (int nf = 0; nf < 8; nf++)
        br[nf] = *(const float2*)(bp + nf * 8 + tig * 2);

    if (EPI_FRAG) {
        __syncthreads();
        // Pre-folded H-blob addressing (derived identical to R13 mapping):
        //   half2 idx = 4*[(wid&1)*1024 + ((wid>>1)*4+mf)*128 + (nf>>1)*32 + tw]
        //               + half + 2*(nf&1),   tw = lid ^ (((lid>>3)&3)<<1)
        const int tw = lid ^ (((lid >> 3) & 3) << 1);
        __half2* sh = (__half2*)smem + (wid & 1) * 4096 + (wid >> 1) * 2048 + tw * 4;
#pragma unroll
        for (int mf = 0; mf < 4; mf++) {
#pragma unroll
            for (int nf = 0; nf < 8; nf++) {
                float v0 = gelu_exact(acc[mf][nf][0] + br[nf].x);
                float v1 = gelu_exact(acc[mf][nf][1] + br[nf].y);
                float v2 = gelu_exact(acc[mf][nf][2] + br[nf].x);
                float v3 = gelu_exact(acc[mf][nf][3] + br[nf].y);
                __half2 h0 = __floats2half2_rn(v0, v1);   // half = 0
                __half2 h1 = __floats2half2_rn(v2, v3);   // half = 1
                uint2 u;
                u.x = *(uint32_t*)&h0;
                u.y = *(uint32_t*)&h1;
                *(uint2*)(sh + mf * 512 + (nf >> 1) * 128 + 2 * (nf & 1)) = u;
            }
        }
        __syncthreads();
        float4* dst = (float4*)((__half*)Cout +
            (((size_t)((e * MTILES + blockIdx.y) * KCH2 + bx * 2)) << 13));
        const float4* st = (const float4*)smem;
#pragma unroll
        for (int u = tid; u < 2048; u += 128) {
            int t = u & 31;
            int twc = t ^ (((t >> 3) & 3) << 1);
            dst[u] = st[(u & ~31) | twc];
        }
    } else {
        float* Cf = (float*)Cout;
#pragma unroll
        for (int mf = 0; mf < 4; mf++)
#pragma unroll
            for (int half = 0; half < 2; half++) {
                int m = m0 + warpM + mf * 16 + gid + half * 8;
                if (m >= Me) continue;
                float* Crow = Cf + (size_t)(e * CAP + m) * NDIM + n0 + warpN + tig * 2;
#pragma unroll
                for (int nf = 0; nf < 8; nf++) {
                    float2 o;
                    o.x = acc[mf][nf][half * 2 + 0] + br[nf].x;
                    o.y = acc[mf][nf][half * 2 + 1] + br[nf].y;
                    *(float2*)(Crow + nf * 8) = o;
                }
            }
    }
}

// ---------------------------------------------------------------------------
// combine + LayerNorm
// ---------------------------------------------------------------------------
__global__ __launch_bounds__(256) void combine_ln_kernel(
    const float* __restrict__ lnw,
    const float* __restrict__ lnb,
    float* __restrict__ out)
{
    const int t   = blockIdx.x;
    const int tid = threadIdx.x;
    const int s0  = g_slot[2 * t + 0];
    const int s1  = g_slot[2 * t + 1];
    const float w0 = g_route_w[2 * t + 0];
    const float w1 = g_route_w[2 * t + 1];

    float v[3];
    float sum = 0.f;
#pragma unroll
    for (int r = 0; r < 3; r++) {
        int i = r * 256 + tid;
        float a = (s0 >= 0) ? g_Y[(size_t)s0 * DIM + i] : 0.f;
        float b = (s1 >= 0) ? g_Y[(size_t)s1 * DIM + i] : 0.f;
        v[r] = w0 * a + w1 * b;
        sum += v[r];
    }

    __shared__ float red[256];
    red[tid] = sum;
    __syncthreads();
#pragma unroll
    for (int o = 128; o > 0; o >>= 1) {
        if (tid < o) red[tid] += red[tid + o];
        __syncthreads();
    }
    float mu = red[0] * (1.f / (float)DIM);
    __syncthreads();

    float sq = 0.f;
#pragma unroll
    for (int r = 0; r < 3; r++) { float d = v[r] - mu; sq += d * d; }
    red[tid] = sq;
    __syncthreads();
#pragma unroll
    for (int o = 128; o > 0; o >>= 1) {
        if (tid < o) red[tid] += red[tid + o];
        __syncthreads();
    }
    float rstd = rsqrtf(red[0] * (1.f / (float)DIM) + 1e-5f);

#pragma unroll
    for (int r = 0; r < 3; r++) {
        int i = r * 256 + tid;
        out[(size_t)t * DIM + i] = (v[r] - mu) * rstd * lnw[i] + lnb[i];
    }
}

// ---------------------------------------------------------------------------
// Launch:  prep(0), assign(1), gather(2), gemm1(3), gemm2(4), combine(5)
// ---------------------------------------------------------------------------
extern "C" void kernel_launch(void* const* d_in, const int* in_sizes, int n_in,
                              void* d_out, int out_size)
{
    const float* x   = (const float*)d_in[0];
    const float* wg  = (const float*)d_in[1];
    const float* w1  = (const float*)d_in[2];
    const float* b1  = (const float*)d_in[3];
    const float* w2  = (const float*)d_in[4];
    const float* b2  = (const float*)d_in[5];
    const float* lnw = (const float*)d_in[6];
    const float* lnb = (const float*)d_in[7];
    float* out = (float*)d_out;

    const int SMEM_BYTES = 3 * 8192 * 4;   // 98304
    cudaFuncSetAttribute(gemm_f16_kernel<KCH1, HID, true>,
                         cudaFuncAttributeMaxDynamicSharedMemorySize, SMEM_BYTES);
    cudaFuncSetAttribute(gemm_f16_kernel<KCH2, DIM, false>,
                         cudaFuncAttributeMaxDynamicSharedMemorySize, SMEM_BYTES);

    __half* w1f; cudaGetSymbolAddress((void**)&w1f, g_w1f);
    __half* w2f; cudaGetSymbolAddress((void**)&w2f, g_w2f);
    __half* xg;  cudaGetSymbolAddress((void**)&xg,  g_xg);
    __half* Hbuf; cudaGetSymbolAddress((void**)&Hbuf, g_H);
    float* Ybuf; cudaGetSymbolAddress((void**)&Ybuf, g_Y);

    prep_kernel<<<4096 + 4608, 256>>>(x, wg, w1, w2);
    assign_kernel<<<N_TOK / 256, 256>>>();
    gather_frag_kernel<<<dim3(CAP / 16, NEXP), 256>>>(x);

    gemm_f16_kernel<KCH1, HID, true><<<dim3(HID / 128, MTILES, NEXP), 128, SMEM_BYTES>>>(
        xg, w1f, b1, Hbuf);
    gemm_f16_kernel<KCH2, DIM, false><<<dim3(DIM / 128, MTILES, NEXP), 128, SMEM_BYTES>>>(
        Hbuf, w2f, b2, Ybuf);

    combine_ln_kernel<<<N_TOK, 256>>>(lnw, lnb, out);
}